// round 13
// baseline (speedup 1.0000x reference)
#include <cuda_runtime.h>
#include <cuda_bf16.h>
#include <math.h>
#include <stdint.h>

// Problem constants
#define BB 16
#define NN 2048
#define CC 768
#define K3 2304           // 3*CC
#define MTOT (BB*NN)      // 32768
#define RSC 0.03608439182435161f   // 1/sqrt(768)
#define PADK 40           // smem row stride (bf16): 80B, 16B-aligned, ldmatrix conflict-free

#define MAT_ELEMS (128 * PADK)            // 5120 bf16 per matrix
#define STAGE_ELEMS (4 * MAT_ELEMS)       // Ah,Al,Bh,Bl
#define SMEM_BYTES (2 * STAGE_ELEMS * 2)  // 81920 (also >= 128*129*4 transpose buf)

// conv halo-A config: 130 rows (+2 pad) shared across the 3 shifts
#define CONV_A_ROWS 132
#define CONV_A_ELEMS (CONV_A_ROWS * PADK)           // per matrix (hi or lo)
#define CONV_STAGE_A (2 * CONV_A_ELEMS)             // hi+lo
#define CONV_STAGE_B (2 * 128 * PADK)               // hi+lo
#define CONV_SMEM ((2 * CONV_STAGE_A + 2 * CONV_STAGE_B) * 2)   // 83200 bytes

// ---------------- scratch (device globals; no allocation allowed) -------------
__device__ __nv_bfloat16 g_xh[(size_t)MTOT * CC];
__device__ __nv_bfloat16 g_xl[(size_t)MTOT * CC];
__device__ __nv_bfloat16 g_wh[CC * K3];             // [o][s*768+i], k-contiguous
__device__ __nv_bfloat16 g_wl[CC * K3];
__device__ float    g_y [(size_t)MTOT * CC];
__device__ __nv_bfloat16 g_yh[(size_t)MTOT * CC];
__device__ __nv_bfloat16 g_yl[(size_t)MTOT * CC];
__device__ float    g_dist[(size_t)BB * NN * NN];   // 268MB pairwise distances
__device__ float    g_knn3[(size_t)MTOT * 64 * 3];  // per-row partial top3
__device__ float    g_sq[MTOT];
__device__ float    g_weight[MTOT];
__device__ float    g_density[MTOT];
__device__ float    g_score[MTOT];
__device__ unsigned g_distmax[BB];
__device__ int      g_centers[BB * 2];
__device__ int      g_idxc[MTOT];
__device__ float    g_allw[BB * 2];
__device__ float    g_partial[BB * 2 * 16 * CC];

// ---------------- helpers ------------------------------------------------------
__device__ __forceinline__ uint32_t smem_u32(const void* p) {
    return (uint32_t)__cvta_generic_to_shared(p);
}
__device__ __forceinline__ void ldsm4(uint32_t* r, uint32_t a) {
    asm volatile("ldmatrix.sync.aligned.m8n8.x4.shared.b16 {%0,%1,%2,%3}, [%4];"
        : "=r"(r[0]), "=r"(r[1]), "=r"(r[2]), "=r"(r[3]) : "r"(a));
}
__device__ __forceinline__ void mma_bf16(float* c, const uint32_t* a, const uint32_t* b) {
    asm volatile("mma.sync.aligned.m16n8k16.row.col.f32.bf16.bf16.f32 "
        "{%0,%1,%2,%3}, {%4,%5,%6,%7}, {%8,%9}, {%0,%1,%2,%3};"
        : "+f"(c[0]), "+f"(c[1]), "+f"(c[2]), "+f"(c[3])
        : "r"(a[0]), "r"(a[1]), "r"(a[2]), "r"(a[3]), "r"(b[0]), "r"(b[1]));
}
__device__ __forceinline__ void cp16(__nv_bfloat16* dst, const __nv_bfloat16* src, int nbytes) {
    asm volatile("cp.async.cg.shared.global [%0], [%1], 16, %2;"
        :: "r"(smem_u32(dst)), "l"(src), "r"(nbytes));
}
__device__ __forceinline__ void cp_commit() { asm volatile("cp.async.commit_group;"); }
template <int N>
__device__ __forceinline__ void cp_wait() { asm volatile("cp.async.wait_group %0;" :: "n"(N)); }

__device__ __forceinline__ void ins3(float v, float& t0, float& t1, float& t2) {
    if (v < t2) {
        if (v < t1) { t2 = t1; if (v < t0) { t1 = t0; t0 = v; } else t1 = v; }
        else t2 = v;
    }
}

// generic 64x32-warp-tile mma for one 32-wide K slice given 4 matrix bases
__device__ __forceinline__ void mma_slice(
    uint32_t Ah_u, uint32_t Al_u, uint32_t Bh_u, uint32_t Bl_u,
    int a_row, int a_k, int b_row, int b_k, float c[4][4][4])
{
#pragma unroll
    for (int ks = 0; ks < 2; ks++) {
        const int kk = ks * 16;
        uint32_t afh[4][4], afl[4][4];
#pragma unroll
        for (int mt = 0; mt < 4; mt++) {
            uint32_t off = ((a_row + mt * 16) * PADK + kk + a_k) * 2;
            ldsm4(afh[mt], Ah_u + off);
            ldsm4(afl[mt], Al_u + off);
        }
        uint32_t bfh[4][2], bfl[4][2];
#pragma unroll
        for (int p = 0; p < 2; p++) {
            uint32_t off = ((b_row + p * 16) * PADK + kk + b_k) * 2;
            uint32_t r[4];
            ldsm4(r, Bh_u + off);
            bfh[2 * p][0] = r[0]; bfh[2 * p][1] = r[1];
            bfh[2 * p + 1][0] = r[2]; bfh[2 * p + 1][1] = r[3];
            ldsm4(r, Bl_u + off);
            bfl[2 * p][0] = r[0]; bfl[2 * p][1] = r[1];
            bfl[2 * p + 1][0] = r[2]; bfl[2 * p + 1][1] = r[3];
        }
#pragma unroll
        for (int mt = 0; mt < 4; mt++)
#pragma unroll
            for (int nt = 0; nt < 4; nt++)
                mma_bf16(c[mt][nt], afh[mt], bfh[nt]);
#pragma unroll
        for (int mt = 0; mt < 4; mt++)
#pragma unroll
            for (int nt = 0; nt < 4; nt++)
                mma_bf16(c[mt][nt], afh[mt], bfl[nt]);
#pragma unroll
        for (int mt = 0; mt < 4; mt++)
#pragma unroll
            for (int nt = 0; nt < 4; nt++)
                mma_bf16(c[mt][nt], afl[mt], bfh[nt]);
    }
}

// ---------------- split fp32 -> bf16 hi/lo (vectorized x4) ---------------------
__global__ void split_kernel(const float* __restrict__ in,
                             __nv_bfloat16* __restrict__ hi,
                             __nv_bfloat16* __restrict__ lo, int n4) {
    int i = blockIdx.x * 256 + threadIdx.x;
    if (i >= n4) return;
    float4 v = reinterpret_cast<const float4*>(in)[i];
    __nv_bfloat16 hx = __float2bfloat16(v.x), hy = __float2bfloat16(v.y);
    __nv_bfloat16 hz = __float2bfloat16(v.z), hw = __float2bfloat16(v.w);
    __nv_bfloat162* h2 = reinterpret_cast<__nv_bfloat162*>(hi);
    __nv_bfloat162* l2 = reinterpret_cast<__nv_bfloat162*>(lo);
    h2[2 * i + 0] = __nv_bfloat162(hx, hy);
    h2[2 * i + 1] = __nv_bfloat162(hz, hw);
    l2[2 * i + 0] = __nv_bfloat162(__float2bfloat16(v.x - __bfloat162float(hx)),
                                   __float2bfloat16(v.y - __bfloat162float(hy)));
    l2[2 * i + 1] = __nv_bfloat162(__float2bfloat16(v.z - __bfloat162float(hz)),
                                   __float2bfloat16(v.w - __bfloat162float(hw)));
}

// ---------------- weight split: w2[o][s*768+i] = conv_w[o][i][s] ---------------
__global__ void wsplit_kernel(const float* __restrict__ w,
                              __nv_bfloat16* __restrict__ hi,
                              __nv_bfloat16* __restrict__ lo) {
    int gid = blockIdx.x * 256 + threadIdx.x;
    if (gid >= CC * K3) return;
    int o = gid / K3;
    int k = gid - o * K3;
    int s = k / CC;
    int i = k - s * CC;
    float v = w[(size_t)o * K3 + i * 3 + s];
    __nv_bfloat16 h = __float2bfloat16(v);
    hi[gid] = h;
    lo[gid] = __float2bfloat16(v - __bfloat162float(h));
}

__global__ void init_kernel(unsigned* dmax) {
    if (threadIdx.x < BB) dmax[threadIdx.x] = 0u;
}

// ---------------- conv GEMM (R11-exact): halo-A reuse, 2-stage, wait<0> --------
__global__ __launch_bounds__(256) void conv_mma_kernel(
    const float* __restrict__ x,
    const __nv_bfloat16* __restrict__ xh, const __nv_bfloat16* __restrict__ xl,
    const __nv_bfloat16* __restrict__ wh, const __nv_bfloat16* __restrict__ wl,
    float* __restrict__ y)
{
    extern __shared__ __nv_bfloat16 smem[];
    __nv_bfloat16* Abuf = smem;                       // 2 stages of halo A (hi+lo)
    __nv_bfloat16* Bbuf = smem + 2 * CONV_STAGE_A;    // 2 stages of B (hi+lo)
    const int tid = threadIdx.x;
    const int m0 = blockIdx.x * 128;
    const int n0 = blockIdx.y * 128;
    const int warp = tid >> 5, lane = tid & 31;
    const int wm = warp >> 2, wn = warp & 3;          // 2x4 warp grid, 64x32 tiles

    const int bz = m0 >> 11;
    const int tokbase = m0 & 2047;

    const int a_row = wm * 64 + (lane & 15);
    const int a_k   = (lane >> 4) * 8;
    const int b_row = wn * 32 + ((lane >> 4) & 1) * 8 + (lane & 7);
    const int b_k   = ((lane >> 3) & 1) * 8;

    const int lrow = tid >> 1, lhalf = (tid & 1) * 16;

    float c[4][4][4];
#pragma unroll
    for (int i = 0; i < 4; i++)
#pragma unroll
        for (int j = 0; j < 4; j++)
#pragma unroll
            for (int q = 0; q < 4; q++) c[i][j][q] = 0.f;

    // A halo tile: 130 rows, row r = token tokbase + r - 1 (zero-filled OOB)
    auto fillA = [&](int stage, int cch) {
        if (tid < 130) {
            const int tokloc = tokbase + tid - 1;
            const int ok = (tokloc >= 0 && tokloc < NN) ? 16 : 0;
            const int tc = tokloc < 0 ? 0 : (tokloc >= NN ? NN - 1 : tokloc);
            const __nv_bfloat16* gah = xh + ((size_t)(bz * NN + tc)) * CC + cch * 32;
            const __nv_bfloat16* gal = xl + ((size_t)(bz * NN + tc)) * CC + cch * 32;
            __nv_bfloat16* d = Abuf + stage * CONV_STAGE_A + tid * PADK;
#pragma unroll
            for (int j = 0; j < 4; j++) {
                cp16(d + j * 8, gah + j * 8, ok);
                cp16(d + CONV_A_ELEMS + j * 8, gal + j * 8, ok);
            }
        }
    };
    auto fillB = [&](int stage, int cch, int s) {
        const int k0 = s * CC + cch * 32;
        const __nv_bfloat16* gbh = wh + (size_t)(n0 + lrow) * K3 + k0 + lhalf;
        const __nv_bfloat16* gbl = wl + (size_t)(n0 + lrow) * K3 + k0 + lhalf;
        __nv_bfloat16* d = Bbuf + stage * CONV_STAGE_B + lrow * PADK + lhalf;
        cp16(d, gbh, 16);                  cp16(d + 8, gbh + 8, 16);
        cp16(d + 128 * PADK, gbl, 16);     cp16(d + 128 * PADK + 8, gbl + 8, 16);
    };

    const int NIT = 72;   // 24 channel chunks x 3 shifts (chunk-major)
    fillA(0, 0);
    fillB(0, 0, 0);
    cp_commit();
    for (int j = 0; j < NIT; j++) {
        const int cch = j / 3, s = j - 3 * cch;
        cp_wait<0>();
        __syncthreads();
        if (j + 1 < NIT) {
            const int c2 = (j + 1) / 3, s2 = (j + 1) - 3 * c2;
            fillB((j + 1) & 1, c2, s2);
            if (s2 == 0) fillA(c2 & 1, c2);
            cp_commit();
        }
        const __nv_bfloat16* Ast = Abuf + (cch & 1) * CONV_STAGE_A;
        const __nv_bfloat16* Bst = Bbuf + (j & 1) * CONV_STAGE_B;
        // shift s selects rows r = ml + s in the halo tile
        mma_slice(smem_u32(Ast) + s * PADK * 2,
                  smem_u32(Ast + CONV_A_ELEMS) + s * PADK * 2,
                  smem_u32(Bst), smem_u32(Bst + 128 * PADK),
                  a_row, a_k, b_row, b_k, c);
    }

    const int g = lane >> 2, t4 = lane & 3;
#pragma unroll
    for (int mt = 0; mt < 4; mt++) {
        int m = m0 + wm * 64 + mt * 16 + g;
        const float* xr0 = x + (size_t)m * CC;
        const float* xr1 = xr0 + (size_t)8 * CC;
        float* yr0 = y + (size_t)m * CC;
        float* yr1 = yr0 + (size_t)8 * CC;
#pragma unroll
        for (int nt = 0; nt < 4; nt++) {
            int n = n0 + wn * 32 + nt * 8 + t4 * 2;
            float2 xi0 = *reinterpret_cast<const float2*>(xr0 + n);
            float2 xi1 = *reinterpret_cast<const float2*>(xr1 + n);
            float2 o0, o1;
            o0.x = xi0.x + c[mt][nt][0]; o0.y = xi0.y + c[mt][nt][1];
            o1.x = xi1.x + c[mt][nt][2]; o1.y = xi1.y + c[mt][nt][3];
            *reinterpret_cast<float2*>(yr0 + n) = o0;
            *reinterpret_cast<float2*>(yr1 + n) = o1;
        }
    }
}

// ---------------- dist GEMM (symmetric) + fused knn partials (R9 config) -------
__global__ __launch_bounds__(256, 2) void dist_mma_kernel(
    const __nv_bfloat16* __restrict__ yh, const __nv_bfloat16* __restrict__ yl,
    const float* __restrict__ sq, float* __restrict__ dist,
    float* __restrict__ part, unsigned* __restrict__ dmax)
{
    extern __shared__ __nv_bfloat16 smem[];
    const int bx = blockIdx.x, by = blockIdx.y;
    if (by < bx) return;                         // lower triangle: mirrored from upper
    const int tid = threadIdx.x;
    const int bz = blockIdx.z;
    const int m0 = bx * 128;
    const int n0 = by * 128;
    const int warp = tid >> 5, lane = tid & 31;
    const int wm = warp >> 2, wn = warp & 3;

    const __nv_bfloat16* Xh = yh + (size_t)bz * NN * CC;
    const __nv_bfloat16* Xl = yl + (size_t)bz * NN * CC;

    const int lrow = tid >> 1, lhalf = (tid & 1) * 16;

    const int a_row = wm * 64 + (lane & 15);
    const int a_k   = (lane >> 4) * 8;
    const int b_row = wn * 32 + ((lane >> 4) & 1) * 8 + (lane & 7);
    const int b_k   = ((lane >> 3) & 1) * 8;

    float c[4][4][4];
#pragma unroll
    for (int i = 0; i < 4; i++)
#pragma unroll
        for (int j = 0; j < 4; j++)
#pragma unroll
            for (int q = 0; q < 4; q++) c[i][j][q] = 0.f;

    const int NIT = CC / 32;

    auto fill = [&](int stage, int k0) {
        __nv_bfloat16* stg = smem + stage * STAGE_ELEMS;
        const __nv_bfloat16* gah = Xh + (size_t)(m0 + lrow) * CC + k0 + lhalf;
        const __nv_bfloat16* gal = Xl + (size_t)(m0 + lrow) * CC + k0 + lhalf;
        const __nv_bfloat16* gbh = Xh + (size_t)(n0 + lrow) * CC + k0 + lhalf;
        const __nv_bfloat16* gbl = Xl + (size_t)(n0 + lrow) * CC + k0 + lhalf;
        __nv_bfloat16* d = stg + lrow * PADK + lhalf;
        cp16(d, gah, 16);                       cp16(d + 8, gah + 8, 16);
        cp16(d + MAT_ELEMS, gal, 16);           cp16(d + MAT_ELEMS + 8, gal + 8, 16);
        cp16(d + 2 * MAT_ELEMS, gbh, 16);       cp16(d + 2 * MAT_ELEMS + 8, gbh + 8, 16);
        cp16(d + 3 * MAT_ELEMS, gbl, 16);       cp16(d + 3 * MAT_ELEMS + 8, gbl + 8, 16);
    };

    fill(0, 0);
    cp_commit();
    for (int it = 0; it < NIT; it++) {
        cp_wait<0>();
        __syncthreads();
        if (it + 1 < NIT) { fill((it + 1) & 1, (it + 1) * 32); cp_commit(); }
        const __nv_bfloat16* stg = smem + (it & 1) * STAGE_ELEMS;
        mma_slice(smem_u32(stg), smem_u32(stg + MAT_ELEMS),
                  smem_u32(stg + 2 * MAT_ELEMS), smem_u32(stg + 3 * MAT_ELEMS),
                  a_row, a_k, b_row, b_k, c);
    }
    __syncthreads();   // all mma reads done before smem reuse as transpose buffer

    const float* sqb = sq + bz * NN;
    const int g = lane >> 2, t4 = lane & 3;
    float* tbuf = reinterpret_cast<float*>(smem);    // 128x129 fp32 transpose buffer
    float lmax = 0.f;
#pragma unroll
    for (int mt = 0; mt < 4; mt++) {
        int ml = wm * 64 + mt * 16 + g;              // local m row (and ml+8)
        int m = m0 + ml;
        float sm0 = sqb[m], sm1 = sqb[m + 8];
        float* dr0 = dist + ((size_t)bz * NN + m) * NN;
        float* dr1 = dr0 + (size_t)8 * NN;
        float p0 = 1e30f, p1 = 1e30f, p2 = 1e30f;    // row m top3 (this 32-col slice)
        float q0 = 1e30f, q1 = 1e30f, q2 = 1e30f;    // row m+8
#pragma unroll
        for (int nt = 0; nt < 4; nt++) {
            int nl = wn * 32 + nt * 8 + t4 * 2;      // local n col (and nl+1)
            int n = n0 + nl;
            float sn0 = sqb[n], sn1 = sqb[n + 1];
            float2 o0, o1;
            o0.x = sqrtf(fmaxf(sm0 + sn0 - 2.f * c[mt][nt][0], 0.f)) * RSC;
            o0.y = sqrtf(fmaxf(sm0 + sn1 - 2.f * c[mt][nt][1], 0.f)) * RSC;
            o1.x = sqrtf(fmaxf(sm1 + sn0 - 2.f * c[mt][nt][2], 0.f)) * RSC;
            o1.y = sqrtf(fmaxf(sm1 + sn1 - 2.f * c[mt][nt][3], 0.f)) * RSC;
            *reinterpret_cast<float2*>(dr0 + n) = o0;
            *reinterpret_cast<float2*>(dr1 + n) = o1;
            if (bx != by) {      // stage transposed values: tbuf[n_local][m_local]
                tbuf[(nl)     * 129 + ml]     = o0.x;
                tbuf[(nl + 1) * 129 + ml]     = o0.y;
                tbuf[(nl)     * 129 + ml + 8] = o1.x;
                tbuf[(nl + 1) * 129 + ml + 8] = o1.y;
            }
            ins3(o0.x, p0, p1, p2); ins3(o0.y, p0, p1, p2);
            ins3(o1.x, q0, q1, q2); ins3(o1.y, q0, q1, q2);
            lmax = fmaxf(lmax, fmaxf(fmaxf(o0.x, o0.y), fmaxf(o1.x, o1.y)));
        }
        // quad merge (lanes g*4+t4 share rows): top3 of 32 cols
#pragma unroll
        for (int off = 1; off <= 2; off <<= 1) {
            float a0 = __shfl_xor_sync(0xffffffffu, p0, off);
            float a1 = __shfl_xor_sync(0xffffffffu, p1, off);
            float a2 = __shfl_xor_sync(0xffffffffu, p2, off);
            ins3(a0, p0, p1, p2); ins3(a1, p0, p1, p2); ins3(a2, p0, p1, p2);
            float b0 = __shfl_xor_sync(0xffffffffu, q0, off);
            float b1 = __shfl_xor_sync(0xffffffffu, q1, off);
            float b2 = __shfl_xor_sync(0xffffffffu, q2, off);
            ins3(b0, q0, q1, q2); ins3(b1, q0, q1, q2); ins3(b2, q0, q1, q2);
        }
        if (t4 == 0) {
            float* pp = part + ((size_t)(bz * NN + m) * 64 + by * 4 + wn) * 3;
            pp[0] = p0; pp[1] = p1; pp[2] = p2;
            float* pq = part + ((size_t)(bz * NN + m + 8) * 64 + by * 4 + wn) * 3;
            pq[0] = q0; pq[1] = q1; pq[2] = q2;
        }
    }
#pragma unroll
    for (int off = 16; off; off >>= 1)
        lmax = fmaxf(lmax, __shfl_xor_sync(0xffffffffu, lmax, off));
    if (lane == 0) atomicMax(&dmax[bz], __float_as_uint(lmax));

    if (bx != by) {              // write mirrored tile + knn partials for rows n0..
        __syncthreads();
        const int r = tid >> 1;             // 0..127
        const int h = (tid & 1) * 64;       // half-row offset
        float* drow = dist + ((size_t)bz * NN + n0 + r) * NN + m0 + h;
        const float* srow = tbuf + r * 129 + h;
        float u0 = 1e30f, u1 = 1e30f, u2 = 1e30f;
#pragma unroll
        for (int j = 0; j < 16; j++) {
            float4 v = make_float4(srow[j * 4 + 0], srow[j * 4 + 1],
                                   srow[j * 4 + 2], srow[j * 4 + 3]);
            *reinterpret_cast<float4*>(drow + j * 4) = v;
            ins3(v.x, u0, u1, u2); ins3(v.y, u0, u1, u2);
            ins3(v.z, u0, u1, u2); ins3(v.w, u0, u1, u2);
        }
        float* pu = part + ((size_t)(bz * NN + n0 + r) * 64 + bx * 4 + (tid & 1)) * 3;
        pu[0] = u0; pu[1] = u1; pu[2] = u2;
        float* pv = part + ((size_t)(bz * NN + n0 + r) * 64 + bx * 4 + 2 + (tid & 1)) * 3;
        pv[0] = 1e30f; pv[1] = 1e30f; pv[2] = 1e30f;
    }
}

// ---------------- knn reduce: top3-of-partials -> density ----------------------
__global__ __launch_bounds__(256) void knn_reduce_kernel(
    const float* __restrict__ part, const float* __restrict__ noise,
    float* __restrict__ density)
{
    int row = (blockIdx.x * 256 + threadIdx.x) >> 5;   // one warp per row
    int lane = threadIdx.x & 31;
    const float* pr = part + (size_t)row * 192;
    float t0 = 1e30f, t1 = 1e30f, t2 = 1e30f;
#pragma unroll
    for (int j = 0; j < 6; j++) ins3(pr[lane + j * 32], t0, t1, t2);
#pragma unroll
    for (int off = 16; off; off >>= 1) {
        float a0 = __shfl_xor_sync(0xffffffffu, t0, off);
        float a1 = __shfl_xor_sync(0xffffffffu, t1, off);
        float a2 = __shfl_xor_sync(0xffffffffu, t2, off);
        ins3(a0, t0, t1, t2); ins3(a1, t0, t1, t2); ins3(a2, t0, t1, t2);
    }
    if (lane == 0) {
        float mean = (t0 * t0 + t1 * t1 + t2 * t2) * (1.0f / 3.0f);
        density[row] = expf(-mean) + noise[row] * 1e-6f;
    }
}

// ---------------- LayerNorm + score + weight + sq + bf16 split (fused) ---------
__global__ __launch_bounds__(256) void ln_kernel(
    float* __restrict__ y, const float* __restrict__ gamma, const float* __restrict__ beta,
    const float* __restrict__ sw, const float* __restrict__ sb,
    float* __restrict__ sq_out, float* __restrict__ w_out,
    __nv_bfloat16* __restrict__ yh, __nv_bfloat16* __restrict__ yl)
{
    int row = blockIdx.x;
    int tid = threadIdx.x;
    __shared__ float ws[8], ws2[8];
    float* xr = y + (size_t)row * CC;
    float v0 = xr[tid], v1 = xr[tid + 256], v2 = xr[tid + 512];

    float s = v0 + v1 + v2;
#pragma unroll
    for (int o = 16; o; o >>= 1) s += __shfl_xor_sync(0xffffffffu, s, o);
    if ((tid & 31) == 0) ws[tid >> 5] = s;
    __syncthreads();
    float mu = (ws[0] + ws[1] + ws[2] + ws[3] + ws[4] + ws[5] + ws[6] + ws[7]) * (1.0f / CC);

    float d0 = v0 - mu, d1 = v1 - mu, d2 = v2 - mu;
    float q = d0 * d0 + d1 * d1 + d2 * d2;
#pragma unroll
    for (int o = 16; o; o >>= 1) q += __shfl_xor_sync(0xffffffffu, q, o);
    __syncthreads();
    if ((tid & 31) == 0) ws[tid >> 5] = q;
    __syncthreads();
    float var = (ws[0] + ws[1] + ws[2] + ws[3] + ws[4] + ws[5] + ws[6] + ws[7]) * (1.0f / CC);
    float inv = 1.0f / sqrtf(var + 1e-5f);

    float x0 = d0 * inv * gamma[tid]       + beta[tid];
    float x1 = d1 * inv * gamma[tid + 256] + beta[tid + 256];
    float x2 = d2 * inv * gamma[tid + 512] + beta[tid + 512];
    xr[tid] = x0; xr[tid + 256] = x1; xr[tid + 512] = x2;

    __nv_bfloat16* hr = yh + (size_t)row * CC;
    __nv_bfloat16* lr = yl + (size_t)row * CC;
    __nv_bfloat16 h0 = __float2bfloat16(x0), h1 = __float2bfloat16(x1), h2 = __float2bfloat16(x2);
    hr[tid] = h0; hr[tid + 256] = h1; hr[tid + 512] = h2;
    lr[tid]       = __float2bfloat16(x0 - __bfloat162float(h0));
    lr[tid + 256] = __float2bfloat16(x1 - __bfloat162float(h1));
    lr[tid + 512] = __float2bfloat16(x2 - __bfloat162float(h2));

    float a = x0 * x0 + x1 * x1 + x2 * x2;
    float b = x0 * sw[tid] + x1 * sw[tid + 256] + x2 * sw[tid + 512];
#pragma unroll
    for (int o = 16; o; o >>= 1) {
        a += __shfl_xor_sync(0xffffffffu, a, o);
        b += __shfl_xor_sync(0xffffffffu, b, o);
    }
    __syncthreads();
    if ((tid & 31) == 0) { ws[tid >> 5] = a; ws2[tid >> 5] = b; }
    __syncthreads();
    if (tid == 0) {
        sq_out[row] = ws[0] + ws[1] + ws[2] + ws[3] + ws[4] + ws[5] + ws[6] + ws[7];
        w_out[row]  = expf(ws2[0] + ws2[1] + ws2[2] + ws2[3] + ws2[4] + ws2[5] + ws2[6] + ws2[7] + sb[0]);
    }
}

// ---------------- dist_min (4 rows per block: share density row) ---------------
__global__ __launch_bounds__(256) void distmin_kernel(
    const float* __restrict__ dist, const float* __restrict__ density,
    const unsigned* __restrict__ dmax, float* __restrict__ score)
{
    int r0 = blockIdx.x * 4;
    int tid = threadIdx.x;
    int b = r0 >> 11;
    const float4* db = reinterpret_cast<const float4*>(density + b * NN);
    float dn[4], lmin[4];
    float dm = __uint_as_float(dmax[b]);
#pragma unroll
    for (int r = 0; r < 4; r++) { dn[r] = density[r0 + r]; lmin[r] = dm; }
#pragma unroll
    for (int it = 0; it < 2; it++) {
        float4 rho = db[tid + it * 256];
#pragma unroll
        for (int r = 0; r < 4; r++) {
            const float4* dr = reinterpret_cast<const float4*>(dist + (size_t)(r0 + r) * NN);
            float4 d = dr[tid + it * 256];
            if (rho.x > dn[r]) lmin[r] = fminf(lmin[r], d.x);
            if (rho.y > dn[r]) lmin[r] = fminf(lmin[r], d.y);
            if (rho.z > dn[r]) lmin[r] = fminf(lmin[r], d.z);
            if (rho.w > dn[r]) lmin[r] = fminf(lmin[r], d.w);
        }
    }
    __shared__ float red[4][256];
#pragma unroll
    for (int r = 0; r < 4; r++) red[r][tid] = lmin[r];
    __syncthreads();
    for (int s = 128; s > 0; s >>= 1) {
        if (tid < s) {
#pragma unroll
            for (int r = 0; r < 4; r++) red[r][tid] = fminf(red[r][tid], red[r][tid + s]);
        }
        __syncthreads();
    }
    if (tid < 4) score[r0 + tid] = red[tid][0] * dn[tid];
}

// ---------------- per-batch top-2 (ties -> lower index) -----------------------
__global__ __launch_bounds__(256) void top2_kernel(const float* __restrict__ score, int* __restrict__ centers) {
    int b = blockIdx.x, tid = threadIdx.x;
    const float* sc = score + b * NN;
    __shared__ float sv[256];
    __shared__ int   si[256];
    float bv = -1e30f; int bi = 0;
    for (int n = tid; n < NN; n += 256) { float v = sc[n]; if (v > bv) { bv = v; bi = n; } }
    sv[tid] = bv; si[tid] = bi;
    __syncthreads();
    for (int s = 128; s > 0; s >>= 1) {
        if (tid < s) {
            if (sv[tid + s] > sv[tid] || (sv[tid + s] == sv[tid] && si[tid + s] < si[tid])) {
                sv[tid] = sv[tid + s]; si[tid] = si[tid + s];
            }
        }
        __syncthreads();
    }
    int c0 = si[0];
    __syncthreads();
    bv = -1e30f; bi = 0;
    for (int n = tid; n < NN; n += 256) {
        if (n == c0) continue;
        float v = sc[n]; if (v > bv) { bv = v; bi = n; }
    }
    sv[tid] = bv; si[tid] = bi;
    __syncthreads();
    for (int s = 128; s > 0; s >>= 1) {
        if (tid < s) {
            if (sv[tid + s] > sv[tid] || (sv[tid + s] == sv[tid] && si[tid + s] < si[tid])) {
                sv[tid] = sv[tid + s]; si[tid] = si[tid + s];
            }
        }
        __syncthreads();
    }
    if (tid == 0) { centers[2 * b] = c0; centers[2 * b + 1] = si[0]; }
}

// ---------------- cluster assignment ------------------------------------------
__global__ void assign_kernel(const float* __restrict__ dist, const int* __restrict__ centers,
                              int* __restrict__ idxc) {
    int gid = blockIdx.x * 256 + threadIdx.x;
    if (gid >= MTOT) return;
    int b = gid >> 11, n = gid & 2047;
    int c0 = centers[2 * b], c1 = centers[2 * b + 1];
    float d0 = dist[((size_t)b * NN + c0) * NN + n];
    float d1 = dist[((size_t)b * NN + c1) * NN + n];
    int id = (d0 <= d1) ? 0 : 1;
    if (n == c0) id = 0;
    if (n == c1) id = 1;
    idxc[gid] = id;
}

// ---------------- all_weight per (b,cluster) ----------------------------------
__global__ __launch_bounds__(256) void allw_kernel(
    const float* __restrict__ weight, const int* __restrict__ idxc, float* __restrict__ allw)
{
    int b = blockIdx.x, tid = threadIdx.x;
    float w0 = 0.f, w1 = 0.f;
    for (int n = tid; n < NN; n += 256) {
        float w = weight[b * NN + n];
        if (idxc[b * NN + n] == 0) w0 += w; else w1 += w;
    }
    __shared__ float r0[256], r1[256];
    r0[tid] = w0; r1[tid] = w1;
    __syncthreads();
    for (int s = 128; s > 0; s >>= 1) {
        if (tid < s) { r0[tid] += r0[tid + s]; r1[tid] += r1[tid + s]; }
        __syncthreads();
    }
    if (tid == 0) { allw[2 * b] = r0[0] + 1e-6f; allw[2 * b + 1] = r1[0] + 1e-6f; }
}

// ---------------- weighted merge: both clusters in one pass -------------------
__global__ __launch_bounds__(256) void merge_partial_kernel(
    const float* __restrict__ x, const float* __restrict__ weight,
    const int* __restrict__ idxc, const float* __restrict__ allw, float* __restrict__ partial)
{
    int chunk = blockIdx.x;   // 0..15
    int b = blockIdx.y;       // 0..15
    int tid = threadIdx.x;
    float aw0 = allw[b * 2], aw1 = allw[b * 2 + 1];
    float a[2][3] = {{0.f, 0.f, 0.f}, {0.f, 0.f, 0.f}};
    for (int j = 0; j < 128; j++) {
        int n = chunk * 128 + j;
        int id = idxc[b * NN + n];
        float w = weight[b * NN + n] / (id ? aw1 : aw0);
        const float* xr = x + ((size_t)b * NN + n) * CC;
        a[id][0] += w * xr[tid];
        a[id][1] += w * xr[tid + 256];
        a[id][2] += w * xr[tid + 512];
    }
#pragma unroll
    for (int cl = 0; cl < 2; cl++) {
        float* p = partial + (((size_t)(b * 2 + cl) * 16 + chunk)) * CC;
        p[tid] = a[cl][0]; p[tid + 256] = a[cl][1]; p[tid + 512] = a[cl][2];
    }
}

__global__ __launch_bounds__(256) void merge_reduce_kernel(
    const float* __restrict__ partial, float* __restrict__ out)
{
    int g = blockIdx.x;
    int tid = threadIdx.x;
#pragma unroll
    for (int t = 0; t < 3; t++) {
        int ch = tid + t * 256;
        float s = 0.f;
        for (int c = 0; c < 16; c++)
            s += partial[((size_t)g * 16 + c) * CC + ch];
        out[(size_t)g * CC + ch] = s;
    }
}

// ---------------- finalize agg_weight + idx outputs ---------------------------
__global__ void finalize_kernel(const float* __restrict__ weight, const int* __restrict__ idxc,
                                const float* __restrict__ allw, float* __restrict__ out)
{
    int gid = blockIdx.x * 256 + threadIdx.x;
    if (gid >= MTOT) return;
    int b = gid >> 11;
    int id = idxc[gid];
    float nw = weight[gid] / allw[b * 2 + id];
    out[24576 + gid] = nw;
    out[57344 + gid] = (float)id;
}

// ------------------------------ launch ----------------------------------------
extern "C" void kernel_launch(void* const* d_in, const int* in_sizes, int n_in,
                              void* d_out, int out_size) {
    const float* x      = (const float*)d_in[0];
    const float* conv_w = (const float*)d_in[1];
    const float* gamma  = (const float*)d_in[2];
    const float* beta   = (const float*)d_in[3];
    const float* sw     = (const float*)d_in[4];
    const float* sb     = (const float*)d_in[5];
    const float* noise  = (const float*)d_in[6];
    float* out = (float*)d_out;

    __nv_bfloat16 *xh, *xl, *wh, *wl, *yh, *yl;
    float *y, *dist, *knn3, *sq, *weight, *density, *score, *allw, *partial;
    unsigned* dmax; int *centers, *idxc;
    cudaGetSymbolAddress((void**)&xh, g_xh);
    cudaGetSymbolAddress((void**)&xl, g_xl);
    cudaGetSymbolAddress((void**)&wh, g_wh);
    cudaGetSymbolAddress((void**)&wl, g_wl);
    cudaGetSymbolAddress((void**)&yh, g_yh);
    cudaGetSymbolAddress((void**)&yl, g_yl);
    cudaGetSymbolAddress((void**)&y, g_y);
    cudaGetSymbolAddress((void**)&dist, g_dist);
    cudaGetSymbolAddress((void**)&knn3, g_knn3);
    cudaGetSymbolAddress((void**)&sq, g_sq);
    cudaGetSymbolAddress((void**)&weight, g_weight);
    cudaGetSymbolAddress((void**)&density, g_density);
    cudaGetSymbolAddress((void**)&score, g_score);
    cudaGetSymbolAddress((void**)&dmax, g_distmax);
    cudaGetSymbolAddress((void**)&centers, g_centers);
    cudaGetSymbolAddress((void**)&idxc, g_idxc);
    cudaGetSymbolAddress((void**)&allw, g_allw);
    cudaGetSymbolAddress((void**)&partial, g_partial);

    // opt-in to >48KB dynamic smem; only outside graph capture (attr persists)
    cudaStreamCaptureStatus cstat = cudaStreamCaptureStatusNone;
    cudaStreamIsCapturing(0, &cstat);
    if (cstat == cudaStreamCaptureStatusNone) {
        cudaFuncSetAttribute(conv_mma_kernel, cudaFuncAttributeMaxDynamicSharedMemorySize, CONV_SMEM);
        cudaFuncSetAttribute(dist_mma_kernel, cudaFuncAttributeMaxDynamicSharedMemorySize, SMEM_BYTES);
    }

    const int n4 = MTOT * CC / 4;

    wsplit_kernel<<<(CC * K3 + 255) / 256, 256>>>(conv_w, wh, wl);
    split_kernel<<<(n4 + 255) / 256, 256>>>(x, xh, xl, n4);
    init_kernel<<<1, 32>>>(dmax);
    conv_mma_kernel<<<dim3(MTOT / 128, CC / 128), 256, CONV_SMEM>>>(x, xh, xl, wh, wl, y);
    ln_kernel<<<MTOT, 256>>>(y, gamma, beta, sw, sb, sq, weight, yh, yl);
    dist_mma_kernel<<<dim3(NN / 128, NN / 128, BB), 256, SMEM_BYTES>>>(yh, yl, sq, dist, knn3, dmax);
    knn_reduce_kernel<<<MTOT * 32 / 256, 256>>>(knn3, noise, density);
    distmin_kernel<<<MTOT / 4, 256>>>(dist, density, dmax, score);
    top2_kernel<<<BB, 256>>>(score, centers);
    assign_kernel<<<MTOT / 256, 256>>>(dist, centers, idxc);
    allw_kernel<<<BB, 256>>>(weight, idxc, allw);
    merge_partial_kernel<<<dim3(16, BB), 256>>>(y, weight, idxc, allw, partial);
    merge_reduce_kernel<<<BB * 2, 256>>>(partial, out);
    finalize_kernel<<<MTOT / 256, 256>>>(weight, idxc, allw, out);
}

// round 14
// speedup vs baseline: 1.0039x; 1.0039x over previous
#include <cuda_runtime.h>
#include <cuda_bf16.h>
#include <math.h>
#include <stdint.h>

// Problem constants
#define BB 16
#define NN 2048
#define CC 768
#define K3 2304           // 3*CC
#define MTOT (BB*NN)      // 32768
#define RSC 0.03608439182435161f   // 1/sqrt(768)
#define PADK 40           // smem row stride (bf16): 80B, 16B-aligned, ldmatrix conflict-free

#define MAT_ELEMS (128 * PADK)            // 5120 bf16 per matrix
#define STAGE_ELEMS (4 * MAT_ELEMS)       // Ah,Al,Bh,Bl
#define SMEM_BYTES (2 * STAGE_ELEMS * 2)  // 81920 (also >= 128*129*4 transpose buf)

// conv halo-A config: 130 rows (+2 pad) shared across the 3 shifts
#define CONV_A_ROWS 132
#define CONV_A_ELEMS (CONV_A_ROWS * PADK)           // per matrix (hi or lo)
#define CONV_STAGE_A (2 * CONV_A_ELEMS)             // hi+lo
#define CONV_STAGE_B (2 * 128 * PADK)               // hi+lo
#define CONV_SMEM ((2 * CONV_STAGE_A + 2 * CONV_STAGE_B) * 2)   // 83200 bytes

// ---------------- scratch (device globals; no allocation allowed) -------------
__device__ __nv_bfloat16 g_xh[(size_t)MTOT * CC];
__device__ __nv_bfloat16 g_xl[(size_t)MTOT * CC];
__device__ __nv_bfloat16 g_wh[CC * K3];             // [o][s*768+i], k-contiguous
__device__ __nv_bfloat16 g_wl[CC * K3];
__device__ float    g_y [(size_t)MTOT * CC];
__device__ __nv_bfloat16 g_yh[(size_t)MTOT * CC];
__device__ __nv_bfloat16 g_yl[(size_t)MTOT * CC];
__device__ float    g_dist[(size_t)BB * NN * NN];   // 268MB pairwise distances
__device__ float    g_knn3[(size_t)MTOT * 64 * 3];  // per-row partial top3
__device__ float    g_sq[MTOT];
__device__ float    g_weight[MTOT];
__device__ float    g_density[MTOT];
__device__ float    g_score[MTOT];
__device__ unsigned g_distmax[BB];
__device__ int      g_centers[BB * 2];
__device__ int      g_idxc[MTOT];
__device__ float    g_allw[BB * 2];
__device__ float    g_partial[BB * 2 * 16 * CC];

// ---------------- helpers ------------------------------------------------------
__device__ __forceinline__ uint32_t smem_u32(const void* p) {
    return (uint32_t)__cvta_generic_to_shared(p);
}
__device__ __forceinline__ void ldsm4(uint32_t* r, uint32_t a) {
    asm volatile("ldmatrix.sync.aligned.m8n8.x4.shared.b16 {%0,%1,%2,%3}, [%4];"
        : "=r"(r[0]), "=r"(r[1]), "=r"(r[2]), "=r"(r[3]) : "r"(a));
}
__device__ __forceinline__ void mma_bf16(float* c, const uint32_t* a, const uint32_t* b) {
    asm volatile("mma.sync.aligned.m16n8k16.row.col.f32.bf16.bf16.f32 "
        "{%0,%1,%2,%3}, {%4,%5,%6,%7}, {%8,%9}, {%0,%1,%2,%3};"
        : "+f"(c[0]), "+f"(c[1]), "+f"(c[2]), "+f"(c[3])
        : "r"(a[0]), "r"(a[1]), "r"(a[2]), "r"(a[3]), "r"(b[0]), "r"(b[1]));
}
__device__ __forceinline__ void cp16(__nv_bfloat16* dst, const __nv_bfloat16* src, int nbytes) {
    asm volatile("cp.async.cg.shared.global [%0], [%1], 16, %2;"
        :: "r"(smem_u32(dst)), "l"(src), "r"(nbytes));
}
__device__ __forceinline__ void cp_commit() { asm volatile("cp.async.commit_group;"); }
template <int N>
__device__ __forceinline__ void cp_wait() { asm volatile("cp.async.wait_group %0;" :: "n"(N)); }

__device__ __forceinline__ void ins3(float v, float& t0, float& t1, float& t2) {
    if (v < t2) {
        if (v < t1) { t2 = t1; if (v < t0) { t1 = t0; t0 = v; } else t1 = v; }
        else t2 = v;
    }
}

// generic 64x32-warp-tile mma for one 32-wide K slice given 4 matrix bases
__device__ __forceinline__ void mma_slice(
    uint32_t Ah_u, uint32_t Al_u, uint32_t Bh_u, uint32_t Bl_u,
    int a_row, int a_k, int b_row, int b_k, float c[4][4][4])
{
#pragma unroll
    for (int ks = 0; ks < 2; ks++) {
        const int kk = ks * 16;
        uint32_t afh[4][4], afl[4][4];
#pragma unroll
        for (int mt = 0; mt < 4; mt++) {
            uint32_t off = ((a_row + mt * 16) * PADK + kk + a_k) * 2;
            ldsm4(afh[mt], Ah_u + off);
            ldsm4(afl[mt], Al_u + off);
        }
        uint32_t bfh[4][2], bfl[4][2];
#pragma unroll
        for (int p = 0; p < 2; p++) {
            uint32_t off = ((b_row + p * 16) * PADK + kk + b_k) * 2;
            uint32_t r[4];
            ldsm4(r, Bh_u + off);
            bfh[2 * p][0] = r[0]; bfh[2 * p][1] = r[1];
            bfh[2 * p + 1][0] = r[2]; bfh[2 * p + 1][1] = r[3];
            ldsm4(r, Bl_u + off);
            bfl[2 * p][0] = r[0]; bfl[2 * p][1] = r[1];
            bfl[2 * p + 1][0] = r[2]; bfl[2 * p + 1][1] = r[3];
        }
#pragma unroll
        for (int mt = 0; mt < 4; mt++)
#pragma unroll
            for (int nt = 0; nt < 4; nt++)
                mma_bf16(c[mt][nt], afh[mt], bfh[nt]);
#pragma unroll
        for (int mt = 0; mt < 4; mt++)
#pragma unroll
            for (int nt = 0; nt < 4; nt++)
                mma_bf16(c[mt][nt], afh[mt], bfl[nt]);
#pragma unroll
        for (int mt = 0; mt < 4; mt++)
#pragma unroll
            for (int nt = 0; nt < 4; nt++)
                mma_bf16(c[mt][nt], afl[mt], bfh[nt]);
    }
}

// ---------------- split fp32 -> bf16 hi/lo (vectorized x4) ---------------------
__global__ void split_kernel(const float* __restrict__ in,
                             __nv_bfloat16* __restrict__ hi,
                             __nv_bfloat16* __restrict__ lo, int n4) {
    int i = blockIdx.x * 256 + threadIdx.x;
    if (i >= n4) return;
    float4 v = reinterpret_cast<const float4*>(in)[i];
    __nv_bfloat16 hx = __float2bfloat16(v.x), hy = __float2bfloat16(v.y);
    __nv_bfloat16 hz = __float2bfloat16(v.z), hw = __float2bfloat16(v.w);
    __nv_bfloat162* h2 = reinterpret_cast<__nv_bfloat162*>(hi);
    __nv_bfloat162* l2 = reinterpret_cast<__nv_bfloat162*>(lo);
    h2[2 * i + 0] = __nv_bfloat162(hx, hy);
    h2[2 * i + 1] = __nv_bfloat162(hz, hw);
    l2[2 * i + 0] = __nv_bfloat162(__float2bfloat16(v.x - __bfloat162float(hx)),
                                   __float2bfloat16(v.y - __bfloat162float(hy)));
    l2[2 * i + 1] = __nv_bfloat162(__float2bfloat16(v.z - __bfloat162float(hz)),
                                   __float2bfloat16(v.w - __bfloat162float(hw)));
}

// ---------------- weight split: w2[o][s*768+i] = conv_w[o][i][s] ---------------
__global__ void wsplit_kernel(const float* __restrict__ w,
                              __nv_bfloat16* __restrict__ hi,
                              __nv_bfloat16* __restrict__ lo) {
    int gid = blockIdx.x * 256 + threadIdx.x;
    if (gid >= CC * K3) return;
    int o = gid / K3;
    int k = gid - o * K3;
    int s = k / CC;
    int i = k - s * CC;
    float v = w[(size_t)o * K3 + i * 3 + s];
    __nv_bfloat16 h = __float2bfloat16(v);
    hi[gid] = h;
    lo[gid] = __float2bfloat16(v - __bfloat162float(h));
}

__global__ void init_kernel(unsigned* dmax) {
    if (threadIdx.x < BB) dmax[threadIdx.x] = 0u;
}

// ---------------- conv GEMM (R11-exact): halo-A reuse, 2-stage, wait<0> --------
__global__ __launch_bounds__(256) void conv_mma_kernel(
    const float* __restrict__ x,
    const __nv_bfloat16* __restrict__ xh, const __nv_bfloat16* __restrict__ xl,
    const __nv_bfloat16* __restrict__ wh, const __nv_bfloat16* __restrict__ wl,
    float* __restrict__ y)
{
    extern __shared__ __nv_bfloat16 smem[];
    __nv_bfloat16* Abuf = smem;                       // 2 stages of halo A (hi+lo)
    __nv_bfloat16* Bbuf = smem + 2 * CONV_STAGE_A;    // 2 stages of B (hi+lo)
    const int tid = threadIdx.x;
    const int m0 = blockIdx.x * 128;
    const int n0 = blockIdx.y * 128;
    const int warp = tid >> 5, lane = tid & 31;
    const int wm = warp >> 2, wn = warp & 3;          // 2x4 warp grid, 64x32 tiles

    const int bz = m0 >> 11;
    const int tokbase = m0 & 2047;

    const int a_row = wm * 64 + (lane & 15);
    const int a_k   = (lane >> 4) * 8;
    const int b_row = wn * 32 + ((lane >> 4) & 1) * 8 + (lane & 7);
    const int b_k   = ((lane >> 3) & 1) * 8;

    const int lrow = tid >> 1, lhalf = (tid & 1) * 16;

    float c[4][4][4];
#pragma unroll
    for (int i = 0; i < 4; i++)
#pragma unroll
        for (int j = 0; j < 4; j++)
#pragma unroll
            for (int q = 0; q < 4; q++) c[i][j][q] = 0.f;

    // A halo tile: 130 rows, row r = token tokbase + r - 1 (zero-filled OOB)
    auto fillA = [&](int stage, int cch) {
        if (tid < 130) {
            const int tokloc = tokbase + tid - 1;
            const int ok = (tokloc >= 0 && tokloc < NN) ? 16 : 0;
            const int tc = tokloc < 0 ? 0 : (tokloc >= NN ? NN - 1 : tokloc);
            const __nv_bfloat16* gah = xh + ((size_t)(bz * NN + tc)) * CC + cch * 32;
            const __nv_bfloat16* gal = xl + ((size_t)(bz * NN + tc)) * CC + cch * 32;
            __nv_bfloat16* d = Abuf + stage * CONV_STAGE_A + tid * PADK;
#pragma unroll
            for (int j = 0; j < 4; j++) {
                cp16(d + j * 8, gah + j * 8, ok);
                cp16(d + CONV_A_ELEMS + j * 8, gal + j * 8, ok);
            }
        }
    };
    auto fillB = [&](int stage, int cch, int s) {
        const int k0 = s * CC + cch * 32;
        const __nv_bfloat16* gbh = wh + (size_t)(n0 + lrow) * K3 + k0 + lhalf;
        const __nv_bfloat16* gbl = wl + (size_t)(n0 + lrow) * K3 + k0 + lhalf;
        __nv_bfloat16* d = Bbuf + stage * CONV_STAGE_B + lrow * PADK + lhalf;
        cp16(d, gbh, 16);                  cp16(d + 8, gbh + 8, 16);
        cp16(d + 128 * PADK, gbl, 16);     cp16(d + 128 * PADK + 8, gbl + 8, 16);
    };

    const int NIT = 72;   // 24 channel chunks x 3 shifts (chunk-major)
    fillA(0, 0);
    fillB(0, 0, 0);
    cp_commit();
    for (int j = 0; j < NIT; j++) {
        const int cch = j / 3, s = j - 3 * cch;
        cp_wait<0>();
        __syncthreads();
        if (j + 1 < NIT) {
            const int c2 = (j + 1) / 3, s2 = (j + 1) - 3 * c2;
            fillB((j + 1) & 1, c2, s2);
            if (s2 == 0) fillA(c2 & 1, c2);
            cp_commit();
        }
        const __nv_bfloat16* Ast = Abuf + (cch & 1) * CONV_STAGE_A;
        const __nv_bfloat16* Bst = Bbuf + (j & 1) * CONV_STAGE_B;
        // shift s selects rows r = ml + s in the halo tile
        mma_slice(smem_u32(Ast) + s * PADK * 2,
                  smem_u32(Ast + CONV_A_ELEMS) + s * PADK * 2,
                  smem_u32(Bst), smem_u32(Bst + 128 * PADK),
                  a_row, a_k, b_row, b_k, c);
    }

    const int g = lane >> 2, t4 = lane & 3;
#pragma unroll
    for (int mt = 0; mt < 4; mt++) {
        int m = m0 + wm * 64 + mt * 16 + g;
        const float* xr0 = x + (size_t)m * CC;
        const float* xr1 = xr0 + (size_t)8 * CC;
        float* yr0 = y + (size_t)m * CC;
        float* yr1 = yr0 + (size_t)8 * CC;
#pragma unroll
        for (int nt = 0; nt < 4; nt++) {
            int n = n0 + wn * 32 + nt * 8 + t4 * 2;
            float2 xi0 = *reinterpret_cast<const float2*>(xr0 + n);
            float2 xi1 = *reinterpret_cast<const float2*>(xr1 + n);
            float2 o0, o1;
            o0.x = xi0.x + c[mt][nt][0]; o0.y = xi0.y + c[mt][nt][1];
            o1.x = xi1.x + c[mt][nt][2]; o1.y = xi1.y + c[mt][nt][3];
            *reinterpret_cast<float2*>(yr0 + n) = o0;
            *reinterpret_cast<float2*>(yr1 + n) = o1;
        }
    }
}

// ---------------- dist GEMM (symmetric) + fused knn partials (R9 config) -------
__global__ __launch_bounds__(256, 2) void dist_mma_kernel(
    const __nv_bfloat16* __restrict__ yh, const __nv_bfloat16* __restrict__ yl,
    const float* __restrict__ sq, float* __restrict__ dist,
    float* __restrict__ part, unsigned* __restrict__ dmax)
{
    extern __shared__ __nv_bfloat16 smem[];
    const int bx = blockIdx.x, by = blockIdx.y;
    if (by < bx) return;                         // lower triangle: mirrored from upper
    const int tid = threadIdx.x;
    const int bz = blockIdx.z;
    const int m0 = bx * 128;
    const int n0 = by * 128;
    const int warp = tid >> 5, lane = tid & 31;
    const int wm = warp >> 2, wn = warp & 3;

    const __nv_bfloat16* Xh = yh + (size_t)bz * NN * CC;
    const __nv_bfloat16* Xl = yl + (size_t)bz * NN * CC;

    const int lrow = tid >> 1, lhalf = (tid & 1) * 16;

    const int a_row = wm * 64 + (lane & 15);
    const int a_k   = (lane >> 4) * 8;
    const int b_row = wn * 32 + ((lane >> 4) & 1) * 8 + (lane & 7);
    const int b_k   = ((lane >> 3) & 1) * 8;

    float c[4][4][4];
#pragma unroll
    for (int i = 0; i < 4; i++)
#pragma unroll
        for (int j = 0; j < 4; j++)
#pragma unroll
            for (int q = 0; q < 4; q++) c[i][j][q] = 0.f;

    const int NIT = CC / 32;

    auto fill = [&](int stage, int k0) {
        __nv_bfloat16* stg = smem + stage * STAGE_ELEMS;
        const __nv_bfloat16* gah = Xh + (size_t)(m0 + lrow) * CC + k0 + lhalf;
        const __nv_bfloat16* gal = Xl + (size_t)(m0 + lrow) * CC + k0 + lhalf;
        const __nv_bfloat16* gbh = Xh + (size_t)(n0 + lrow) * CC + k0 + lhalf;
        const __nv_bfloat16* gbl = Xl + (size_t)(n0 + lrow) * CC + k0 + lhalf;
        __nv_bfloat16* d = stg + lrow * PADK + lhalf;
        cp16(d, gah, 16);                       cp16(d + 8, gah + 8, 16);
        cp16(d + MAT_ELEMS, gal, 16);           cp16(d + MAT_ELEMS + 8, gal + 8, 16);
        cp16(d + 2 * MAT_ELEMS, gbh, 16);       cp16(d + 2 * MAT_ELEMS + 8, gbh + 8, 16);
        cp16(d + 3 * MAT_ELEMS, gbl, 16);       cp16(d + 3 * MAT_ELEMS + 8, gbl + 8, 16);
    };

    fill(0, 0);
    cp_commit();
    for (int it = 0; it < NIT; it++) {
        cp_wait<0>();
        __syncthreads();
        if (it + 1 < NIT) { fill((it + 1) & 1, (it + 1) * 32); cp_commit(); }
        const __nv_bfloat16* stg = smem + (it & 1) * STAGE_ELEMS;
        mma_slice(smem_u32(stg), smem_u32(stg + MAT_ELEMS),
                  smem_u32(stg + 2 * MAT_ELEMS), smem_u32(stg + 3 * MAT_ELEMS),
                  a_row, a_k, b_row, b_k, c);
    }
    __syncthreads();   // all mma reads done before smem reuse as transpose buffer

    const float* sqb = sq + bz * NN;
    const int g = lane >> 2, t4 = lane & 3;
    float* tbuf = reinterpret_cast<float*>(smem);    // 128x129 fp32 transpose buffer
    float lmax = 0.f;
#pragma unroll
    for (int mt = 0; mt < 4; mt++) {
        int ml = wm * 64 + mt * 16 + g;              // local m row (and ml+8)
        int m = m0 + ml;
        float sm0 = sqb[m], sm1 = sqb[m + 8];
        float* dr0 = dist + ((size_t)bz * NN + m) * NN;
        float* dr1 = dr0 + (size_t)8 * NN;
        float p0 = 1e30f, p1 = 1e30f, p2 = 1e30f;    // row m top3 (this 32-col slice)
        float q0 = 1e30f, q1 = 1e30f, q2 = 1e30f;    // row m+8
#pragma unroll
        for (int nt = 0; nt < 4; nt++) {
            int nl = wn * 32 + nt * 8 + t4 * 2;      // local n col (and nl+1)
            int n = n0 + nl;
            float sn0 = sqb[n], sn1 = sqb[n + 1];
            float2 o0, o1;
            o0.x = sqrtf(fmaxf(sm0 + sn0 - 2.f * c[mt][nt][0], 0.f)) * RSC;
            o0.y = sqrtf(fmaxf(sm0 + sn1 - 2.f * c[mt][nt][1], 0.f)) * RSC;
            o1.x = sqrtf(fmaxf(sm1 + sn0 - 2.f * c[mt][nt][2], 0.f)) * RSC;
            o1.y = sqrtf(fmaxf(sm1 + sn1 - 2.f * c[mt][nt][3], 0.f)) * RSC;
            *reinterpret_cast<float2*>(dr0 + n) = o0;
            *reinterpret_cast<float2*>(dr1 + n) = o1;
            if (bx != by) {      // stage transposed values: tbuf[n_local][m_local]
                tbuf[(nl)     * 129 + ml]     = o0.x;
                tbuf[(nl + 1) * 129 + ml]     = o0.y;
                tbuf[(nl)     * 129 + ml + 8] = o1.x;
                tbuf[(nl + 1) * 129 + ml + 8] = o1.y;
            }
            ins3(o0.x, p0, p1, p2); ins3(o0.y, p0, p1, p2);
            ins3(o1.x, q0, q1, q2); ins3(o1.y, q0, q1, q2);
            lmax = fmaxf(lmax, fmaxf(fmaxf(o0.x, o0.y), fmaxf(o1.x, o1.y)));
        }
        // quad merge (lanes g*4+t4 share rows): top3 of 32 cols
#pragma unroll
        for (int off = 1; off <= 2; off <<= 1) {
            float a0 = __shfl_xor_sync(0xffffffffu, p0, off);
            float a1 = __shfl_xor_sync(0xffffffffu, p1, off);
            float a2 = __shfl_xor_sync(0xffffffffu, p2, off);
            ins3(a0, p0, p1, p2); ins3(a1, p0, p1, p2); ins3(a2, p0, p1, p2);
            float b0 = __shfl_xor_sync(0xffffffffu, q0, off);
            float b1 = __shfl_xor_sync(0xffffffffu, q1, off);
            float b2 = __shfl_xor_sync(0xffffffffu, q2, off);
            ins3(b0, q0, q1, q2); ins3(b1, q0, q1, q2); ins3(b2, q0, q1, q2);
        }
        if (t4 == 0) {
            float* pp = part + ((size_t)(bz * NN + m) * 64 + by * 4 + wn) * 3;
            pp[0] = p0; pp[1] = p1; pp[2] = p2;
            float* pq = part + ((size_t)(bz * NN + m + 8) * 64 + by * 4 + wn) * 3;
            pq[0] = q0; pq[1] = q1; pq[2] = q2;
        }
    }
#pragma unroll
    for (int off = 16; off; off >>= 1)
        lmax = fmaxf(lmax, __shfl_xor_sync(0xffffffffu, lmax, off));
    if (lane == 0) atomicMax(&dmax[bz], __float_as_uint(lmax));

    if (bx != by) {              // write mirrored tile + knn partials for rows n0..
        __syncthreads();
        const int r = tid >> 1;             // 0..127
        const int h = (tid & 1) * 64;       // half-row offset
        float* drow = dist + ((size_t)bz * NN + n0 + r) * NN + m0 + h;
        const float* srow = tbuf + r * 129 + h;
        float u0 = 1e30f, u1 = 1e30f, u2 = 1e30f;
#pragma unroll
        for (int j = 0; j < 16; j++) {
            float4 v = make_float4(srow[j * 4 + 0], srow[j * 4 + 1],
                                   srow[j * 4 + 2], srow[j * 4 + 3]);
            *reinterpret_cast<float4*>(drow + j * 4) = v;
            ins3(v.x, u0, u1, u2); ins3(v.y, u0, u1, u2);
            ins3(v.z, u0, u1, u2); ins3(v.w, u0, u1, u2);
        }
        float* pu = part + ((size_t)(bz * NN + n0 + r) * 64 + bx * 4 + (tid & 1)) * 3;
        pu[0] = u0; pu[1] = u1; pu[2] = u2;
        float* pv = part + ((size_t)(bz * NN + n0 + r) * 64 + bx * 4 + 2 + (tid & 1)) * 3;
        pv[0] = 1e30f; pv[1] = 1e30f; pv[2] = 1e30f;
    }
}

// ---------------- knn reduce: top3-of-partials -> density ----------------------
__global__ __launch_bounds__(256) void knn_reduce_kernel(
    const float* __restrict__ part, const float* __restrict__ noise,
    float* __restrict__ density)
{
    int row = (blockIdx.x * 256 + threadIdx.x) >> 5;   // one warp per row
    int lane = threadIdx.x & 31;
    const float* pr = part + (size_t)row * 192;
    float t0 = 1e30f, t1 = 1e30f, t2 = 1e30f;
#pragma unroll
    for (int j = 0; j < 6; j++) ins3(pr[lane + j * 32], t0, t1, t2);
#pragma unroll
    for (int off = 16; off; off >>= 1) {
        float a0 = __shfl_xor_sync(0xffffffffu, t0, off);
        float a1 = __shfl_xor_sync(0xffffffffu, t1, off);
        float a2 = __shfl_xor_sync(0xffffffffu, t2, off);
        ins3(a0, t0, t1, t2); ins3(a1, t0, t1, t2); ins3(a2, t0, t1, t2);
    }
    if (lane == 0) {
        float mean = (t0 * t0 + t1 * t1 + t2 * t2) * (1.0f / 3.0f);
        density[row] = expf(-mean) + noise[row] * 1e-6f;
    }
}

// ---------------- LayerNorm + score + weight + sq + bf16 split (fused) ---------
__global__ __launch_bounds__(256) void ln_kernel(
    float* __restrict__ y, const float* __restrict__ gamma, const float* __restrict__ beta,
    const float* __restrict__ sw, const float* __restrict__ sb,
    float* __restrict__ sq_out, float* __restrict__ w_out,
    __nv_bfloat16* __restrict__ yh, __nv_bfloat16* __restrict__ yl)
{
    int row = blockIdx.x;
    int tid = threadIdx.x;
    __shared__ float ws[8], ws2[8];
    float* xr = y + (size_t)row * CC;
    float v0 = xr[tid], v1 = xr[tid + 256], v2 = xr[tid + 512];

    float s = v0 + v1 + v2;
#pragma unroll
    for (int o = 16; o; o >>= 1) s += __shfl_xor_sync(0xffffffffu, s, o);
    if ((tid & 31) == 0) ws[tid >> 5] = s;
    __syncthreads();
    float mu = (ws[0] + ws[1] + ws[2] + ws[3] + ws[4] + ws[5] + ws[6] + ws[7]) * (1.0f / CC);

    float d0 = v0 - mu, d1 = v1 - mu, d2 = v2 - mu;
    float q = d0 * d0 + d1 * d1 + d2 * d2;
#pragma unroll
    for (int o = 16; o; o >>= 1) q += __shfl_xor_sync(0xffffffffu, q, o);
    __syncthreads();
    if ((tid & 31) == 0) ws[tid >> 5] = q;
    __syncthreads();
    float var = (ws[0] + ws[1] + ws[2] + ws[3] + ws[4] + ws[5] + ws[6] + ws[7]) * (1.0f / CC);
    float inv = 1.0f / sqrtf(var + 1e-5f);

    float x0 = d0 * inv * gamma[tid]       + beta[tid];
    float x1 = d1 * inv * gamma[tid + 256] + beta[tid + 256];
    float x2 = d2 * inv * gamma[tid + 512] + beta[tid + 512];
    xr[tid] = x0; xr[tid + 256] = x1; xr[tid + 512] = x2;

    __nv_bfloat16* hr = yh + (size_t)row * CC;
    __nv_bfloat16* lr = yl + (size_t)row * CC;
    __nv_bfloat16 h0 = __float2bfloat16(x0), h1 = __float2bfloat16(x1), h2 = __float2bfloat16(x2);
    hr[tid] = h0; hr[tid + 256] = h1; hr[tid + 512] = h2;
    lr[tid]       = __float2bfloat16(x0 - __bfloat162float(h0));
    lr[tid + 256] = __float2bfloat16(x1 - __bfloat162float(h1));
    lr[tid + 512] = __float2bfloat16(x2 - __bfloat162float(h2));

    float a = x0 * x0 + x1 * x1 + x2 * x2;
    float b = x0 * sw[tid] + x1 * sw[tid + 256] + x2 * sw[tid + 512];
#pragma unroll
    for (int o = 16; o; o >>= 1) {
        a += __shfl_xor_sync(0xffffffffu, a, o);
        b += __shfl_xor_sync(0xffffffffu, b, o);
    }
    __syncthreads();
    if ((tid & 31) == 0) { ws[tid >> 5] = a; ws2[tid >> 5] = b; }
    __syncthreads();
    if (tid == 0) {
        sq_out[row] = ws[0] + ws[1] + ws[2] + ws[3] + ws[4] + ws[5] + ws[6] + ws[7];
        w_out[row]  = expf(ws2[0] + ws2[1] + ws2[2] + ws2[3] + ws2[4] + ws2[5] + ws2[6] + ws2[7] + sb[0]);
    }
}

// ---------------- dist_min (4 rows per block: share density row) ---------------
__global__ __launch_bounds__(256) void distmin_kernel(
    const float* __restrict__ dist, const float* __restrict__ density,
    const unsigned* __restrict__ dmax, float* __restrict__ score)
{
    int r0 = blockIdx.x * 4;
    int tid = threadIdx.x;
    int b = r0 >> 11;
    const float4* db = reinterpret_cast<const float4*>(density + b * NN);
    float dn[4], lmin[4];
    float dm = __uint_as_float(dmax[b]);
#pragma unroll
    for (int r = 0; r < 4; r++) { dn[r] = density[r0 + r]; lmin[r] = dm; }
#pragma unroll
    for (int it = 0; it < 2; it++) {
        float4 rho = db[tid + it * 256];
#pragma unroll
        for (int r = 0; r < 4; r++) {
            const float4* dr = reinterpret_cast<const float4*>(dist + (size_t)(r0 + r) * NN);
            float4 d = dr[tid + it * 256];
            if (rho.x > dn[r]) lmin[r] = fminf(lmin[r], d.x);
            if (rho.y > dn[r]) lmin[r] = fminf(lmin[r], d.y);
            if (rho.z > dn[r]) lmin[r] = fminf(lmin[r], d.z);
            if (rho.w > dn[r]) lmin[r] = fminf(lmin[r], d.w);
        }
    }
    __shared__ float red[4][256];
#pragma unroll
    for (int r = 0; r < 4; r++) red[r][tid] = lmin[r];
    __syncthreads();
    for (int s = 128; s > 0; s >>= 1) {
        if (tid < s) {
#pragma unroll
            for (int r = 0; r < 4; r++) red[r][tid] = fminf(red[r][tid], red[r][tid + s]);
        }
        __syncthreads();
    }
    if (tid < 4) score[r0 + tid] = red[tid][0] * dn[tid];
}

// ---------------- per-batch top-2 (ties -> lower index) -----------------------
__global__ __launch_bounds__(256) void top2_kernel(const float* __restrict__ score, int* __restrict__ centers) {
    int b = blockIdx.x, tid = threadIdx.x;
    const float* sc = score + b * NN;
    __shared__ float sv[256];
    __shared__ int   si[256];
    float bv = -1e30f; int bi = 0;
    for (int n = tid; n < NN; n += 256) { float v = sc[n]; if (v > bv) { bv = v; bi = n; } }
    sv[tid] = bv; si[tid] = bi;
    __syncthreads();
    for (int s = 128; s > 0; s >>= 1) {
        if (tid < s) {
            if (sv[tid + s] > sv[tid] || (sv[tid + s] == sv[tid] && si[tid + s] < si[tid])) {
                sv[tid] = sv[tid + s]; si[tid] = si[tid + s];
            }
        }
        __syncthreads();
    }
    int c0 = si[0];
    __syncthreads();
    bv = -1e30f; bi = 0;
    for (int n = tid; n < NN; n += 256) {
        if (n == c0) continue;
        float v = sc[n]; if (v > bv) { bv = v; bi = n; }
    }
    sv[tid] = bv; si[tid] = bi;
    __syncthreads();
    for (int s = 128; s > 0; s >>= 1) {
        if (tid < s) {
            if (sv[tid + s] > sv[tid] || (sv[tid + s] == sv[tid] && si[tid + s] < si[tid])) {
                sv[tid] = sv[tid + s]; si[tid] = si[tid + s];
            }
        }
        __syncthreads();
    }
    if (tid == 0) { centers[2 * b] = c0; centers[2 * b + 1] = si[0]; }
}

// ---------------- cluster assignment ------------------------------------------
__global__ void assign_kernel(const float* __restrict__ dist, const int* __restrict__ centers,
                              int* __restrict__ idxc) {
    int gid = blockIdx.x * 256 + threadIdx.x;
    if (gid >= MTOT) return;
    int b = gid >> 11, n = gid & 2047;
    int c0 = centers[2 * b], c1 = centers[2 * b + 1];
    float d0 = dist[((size_t)b * NN + c0) * NN + n];
    float d1 = dist[((size_t)b * NN + c1) * NN + n];
    int id = (d0 <= d1) ? 0 : 1;
    if (n == c0) id = 0;
    if (n == c1) id = 1;
    idxc[gid] = id;
}

// ---------------- all_weight per (b,cluster) ----------------------------------
__global__ __launch_bounds__(256) void allw_kernel(
    const float* __restrict__ weight, const int* __restrict__ idxc, float* __restrict__ allw)
{
    int b = blockIdx.x, tid = threadIdx.x;
    float w0 = 0.f, w1 = 0.f;
    for (int n = tid; n < NN; n += 256) {
        float w = weight[b * NN + n];
        if (idxc[b * NN + n] == 0) w0 += w; else w1 += w;
    }
    __shared__ float r0[256], r1[256];
    r0[tid] = w0; r1[tid] = w1;
    __syncthreads();
    for (int s = 128; s > 0; s >>= 1) {
        if (tid < s) { r0[tid] += r0[tid + s]; r1[tid] += r1[tid + s]; }
        __syncthreads();
    }
    if (tid == 0) { allw[2 * b] = r0[0] + 1e-6f; allw[2 * b + 1] = r1[0] + 1e-6f; }
}

// ---------------- weighted merge: both clusters, uniform branch (no spills) ----
__global__ __launch_bounds__(256) void merge_partial_kernel(
    const float* __restrict__ x, const float* __restrict__ weight,
    const int* __restrict__ idxc, const float* __restrict__ allw, float* __restrict__ partial)
{
    int chunk = blockIdx.x;   // 0..15
    int b = blockIdx.y;       // 0..15
    int tid = threadIdx.x;
    float aw0 = allw[b * 2], aw1 = allw[b * 2 + 1];
    float a00 = 0.f, a01 = 0.f, a02 = 0.f;   // cluster 0 accumulators
    float a10 = 0.f, a11 = 0.f, a12 = 0.f;   // cluster 1 accumulators
    for (int j = 0; j < 128; j++) {
        int n = chunk * 128 + j;
        int id = idxc[b * NN + n];           // uniform across the block
        const float* xr = x + ((size_t)b * NN + n) * CC;
        float v0 = xr[tid], v1 = xr[tid + 256], v2 = xr[tid + 512];
        if (id == 0) {
            float w = weight[b * NN + n] / aw0;
            a00 += w * v0; a01 += w * v1; a02 += w * v2;
        } else {
            float w = weight[b * NN + n] / aw1;
            a10 += w * v0; a11 += w * v1; a12 += w * v2;
        }
    }
    float* p0 = partial + (((size_t)(b * 2 + 0) * 16 + chunk)) * CC;
    p0[tid] = a00; p0[tid + 256] = a01; p0[tid + 512] = a02;
    float* p1 = partial + (((size_t)(b * 2 + 1) * 16 + chunk)) * CC;
    p1[tid] = a10; p1[tid + 256] = a11; p1[tid + 512] = a12;
}

__global__ __launch_bounds__(256) void merge_reduce_kernel(
    const float* __restrict__ partial, float* __restrict__ out)
{
    int g = blockIdx.x;
    int tid = threadIdx.x;
#pragma unroll
    for (int t = 0; t < 3; t++) {
        int ch = tid + t * 256;
        float s = 0.f;
        for (int c = 0; c < 16; c++)
            s += partial[((size_t)g * 16 + c) * CC + ch];
        out[(size_t)g * CC + ch] = s;
    }
}

// ---------------- finalize agg_weight + idx outputs ---------------------------
__global__ void finalize_kernel(const float* __restrict__ weight, const int* __restrict__ idxc,
                                const float* __restrict__ allw, float* __restrict__ out)
{
    int gid = blockIdx.x * 256 + threadIdx.x;
    if (gid >= MTOT) return;
    int b = gid >> 11;
    int id = idxc[gid];
    float nw = weight[gid] / allw[b * 2 + id];
    out[24576 + gid] = nw;
    out[57344 + gid] = (float)id;
}

// ------------------------------ launch ----------------------------------------
extern "C" void kernel_launch(void* const* d_in, const int* in_sizes, int n_in,
                              void* d_out, int out_size) {
    const float* x      = (const float*)d_in[0];
    const float* conv_w = (const float*)d_in[1];
    const float* gamma  = (const float*)d_in[2];
    const float* beta   = (const float*)d_in[3];
    const float* sw     = (const float*)d_in[4];
    const float* sb     = (const float*)d_in[5];
    const float* noise  = (const float*)d_in[6];
    float* out = (float*)d_out;

    __nv_bfloat16 *xh, *xl, *wh, *wl, *yh, *yl;
    float *y, *dist, *knn3, *sq, *weight, *density, *score, *allw, *partial;
    unsigned* dmax; int *centers, *idxc;
    cudaGetSymbolAddress((void**)&xh, g_xh);
    cudaGetSymbolAddress((void**)&xl, g_xl);
    cudaGetSymbolAddress((void**)&wh, g_wh);
    cudaGetSymbolAddress((void**)&wl, g_wl);
    cudaGetSymbolAddress((void**)&yh, g_yh);
    cudaGetSymbolAddress((void**)&yl, g_yl);
    cudaGetSymbolAddress((void**)&y, g_y);
    cudaGetSymbolAddress((void**)&dist, g_dist);
    cudaGetSymbolAddress((void**)&knn3, g_knn3);
    cudaGetSymbolAddress((void**)&sq, g_sq);
    cudaGetSymbolAddress((void**)&weight, g_weight);
    cudaGetSymbolAddress((void**)&density, g_density);
    cudaGetSymbolAddress((void**)&score, g_score);
    cudaGetSymbolAddress((void**)&dmax, g_distmax);
    cudaGetSymbolAddress((void**)&centers, g_centers);
    cudaGetSymbolAddress((void**)&idxc, g_idxc);
    cudaGetSymbolAddress((void**)&allw, g_allw);
    cudaGetSymbolAddress((void**)&partial, g_partial);

    // opt-in to >48KB dynamic smem; only outside graph capture (attr persists)
    cudaStreamCaptureStatus cstat = cudaStreamCaptureStatusNone;
    cudaStreamIsCapturing(0, &cstat);
    if (cstat == cudaStreamCaptureStatusNone) {
        cudaFuncSetAttribute(conv_mma_kernel, cudaFuncAttributeMaxDynamicSharedMemorySize, CONV_SMEM);
        cudaFuncSetAttribute(dist_mma_kernel, cudaFuncAttributeMaxDynamicSharedMemorySize, SMEM_BYTES);
    }

    const int n4 = MTOT * CC / 4;

    wsplit_kernel<<<(CC * K3 + 255) / 256, 256>>>(conv_w, wh, wl);
    split_kernel<<<(n4 + 255) / 256, 256>>>(x, xh, xl, n4);
    init_kernel<<<1, 32>>>(dmax);
    conv_mma_kernel<<<dim3(MTOT / 128, CC / 128), 256, CONV_SMEM>>>(x, xh, xl, wh, wl, y);
    ln_kernel<<<MTOT, 256>>>(y, gamma, beta, sw, sb, sq, weight, yh, yl);
    dist_mma_kernel<<<dim3(NN / 128, NN / 128, BB), 256, SMEM_BYTES>>>(yh, yl, sq, dist, knn3, dmax);
    knn_reduce_kernel<<<MTOT * 32 / 256, 256>>>(knn3, noise, density);
    distmin_kernel<<<MTOT / 4, 256>>>(dist, density, dmax, score);
    top2_kernel<<<BB, 256>>>(score, centers);
    assign_kernel<<<MTOT / 256, 256>>>(dist, centers, idxc);
    allw_kernel<<<BB, 256>>>(weight, idxc, allw);
    merge_partial_kernel<<<dim3(16, BB), 256>>>(y, weight, idxc, allw, partial);
    merge_reduce_kernel<<<BB * 2, 256>>>(partial, out);
    finalize_kernel<<<MTOT / 256, 256>>>(weight, idxc, allw, out);
}

// round 15
// speedup vs baseline: 1.0123x; 1.0084x over previous
#include <cuda_runtime.h>
#include <cuda_bf16.h>
#include <math.h>
#include <stdint.h>

// Problem constants
#define BB 16
#define NN 2048
#define CC 768
#define K3 2304           // 3*CC
#define MTOT (BB*NN)      // 32768
#define RSC 0.03608439182435161f   // 1/sqrt(768)
#define PADK 40           // smem row stride (bf16): 80B, 16B-aligned, ldmatrix conflict-free

#define MAT_ELEMS (128 * PADK)            // 5120 bf16 per matrix
#define STAGE_ELEMS (4 * MAT_ELEMS)       // Ah,Al,Bh,Bl
#define SMEM_BYTES (2 * STAGE_ELEMS * 2)  // 81920 (also >= 128*129*4 transpose buf)

// conv halo-A config: 130 rows (+2 pad) shared across the 3 shifts
#define CONV_A_ROWS 132
#define CONV_A_ELEMS (CONV_A_ROWS * PADK)           // per matrix (hi or lo)
#define CONV_STAGE_A (2 * CONV_A_ELEMS)             // hi+lo
#define CONV_STAGE_B (2 * 128 * PADK)               // hi+lo
#define CONV_SMEM ((2 * CONV_STAGE_A + 2 * CONV_STAGE_B) * 2)   // 83200 bytes

// ---------------- scratch (device globals; no allocation allowed) -------------
__device__ __nv_bfloat16 g_xh[(size_t)MTOT * CC];
__device__ __nv_bfloat16 g_xl[(size_t)MTOT * CC];
__device__ __nv_bfloat16 g_wh[CC * K3];             // [o][s*768+i], k-contiguous
__device__ __nv_bfloat16 g_wl[CC * K3];
__device__ float    g_y [(size_t)MTOT * CC];
__device__ __nv_bfloat16 g_yh[(size_t)MTOT * CC];
__device__ __nv_bfloat16 g_yl[(size_t)MTOT * CC];
__device__ float    g_dist[(size_t)BB * NN * NN];   // 268MB pairwise distances
__device__ float    g_knn3[(size_t)MTOT * 64 * 3];  // per-row partial top3
__device__ float    g_sq[MTOT];
__device__ float    g_weight[MTOT];
__device__ float    g_density[MTOT];
__device__ float    g_score[MTOT];
__device__ unsigned g_distmax[BB];
__device__ int      g_centers[BB * 2];
__device__ int      g_idxc[MTOT];
__device__ float    g_allw[BB * 2];
__device__ float    g_partial[BB * 2 * 16 * CC];

// ---------------- helpers ------------------------------------------------------
__device__ __forceinline__ uint32_t smem_u32(const void* p) {
    return (uint32_t)__cvta_generic_to_shared(p);
}
__device__ __forceinline__ void ldsm4(uint32_t* r, uint32_t a) {
    asm volatile("ldmatrix.sync.aligned.m8n8.x4.shared.b16 {%0,%1,%2,%3}, [%4];"
        : "=r"(r[0]), "=r"(r[1]), "=r"(r[2]), "=r"(r[3]) : "r"(a));
}
__device__ __forceinline__ void mma_bf16(float* c, const uint32_t* a, const uint32_t* b) {
    asm volatile("mma.sync.aligned.m16n8k16.row.col.f32.bf16.bf16.f32 "
        "{%0,%1,%2,%3}, {%4,%5,%6,%7}, {%8,%9}, {%0,%1,%2,%3};"
        : "+f"(c[0]), "+f"(c[1]), "+f"(c[2]), "+f"(c[3])
        : "r"(a[0]), "r"(a[1]), "r"(a[2]), "r"(a[3]), "r"(b[0]), "r"(b[1]));
}
__device__ __forceinline__ void cp16(__nv_bfloat16* dst, const __nv_bfloat16* src, int nbytes) {
    asm volatile("cp.async.cg.shared.global [%0], [%1], 16, %2;"
        :: "r"(smem_u32(dst)), "l"(src), "r"(nbytes));
}
__device__ __forceinline__ void cp_commit() { asm volatile("cp.async.commit_group;"); }
template <int N>
__device__ __forceinline__ void cp_wait() { asm volatile("cp.async.wait_group %0;" :: "n"(N)); }

__device__ __forceinline__ void ins3(float v, float& t0, float& t1, float& t2) {
    if (v < t2) {
        if (v < t1) { t2 = t1; if (v < t0) { t1 = t0; t0 = v; } else t1 = v; }
        else t2 = v;
    }
}

// generic 64x32-warp-tile mma for one 32-wide K slice given 4 matrix bases
__device__ __forceinline__ void mma_slice(
    uint32_t Ah_u, uint32_t Al_u, uint32_t Bh_u, uint32_t Bl_u,
    int a_row, int a_k, int b_row, int b_k, float c[4][4][4])
{
#pragma unroll
    for (int ks = 0; ks < 2; ks++) {
        const int kk = ks * 16;
        uint32_t afh[4][4], afl[4][4];
#pragma unroll
        for (int mt = 0; mt < 4; mt++) {
            uint32_t off = ((a_row + mt * 16) * PADK + kk + a_k) * 2;
            ldsm4(afh[mt], Ah_u + off);
            ldsm4(afl[mt], Al_u + off);
        }
        uint32_t bfh[4][2], bfl[4][2];
#pragma unroll
        for (int p = 0; p < 2; p++) {
            uint32_t off = ((b_row + p * 16) * PADK + kk + b_k) * 2;
            uint32_t r[4];
            ldsm4(r, Bh_u + off);
            bfh[2 * p][0] = r[0]; bfh[2 * p][1] = r[1];
            bfh[2 * p + 1][0] = r[2]; bfh[2 * p + 1][1] = r[3];
            ldsm4(r, Bl_u + off);
            bfl[2 * p][0] = r[0]; bfl[2 * p][1] = r[1];
            bfl[2 * p + 1][0] = r[2]; bfl[2 * p + 1][1] = r[3];
        }
#pragma unroll
        for (int mt = 0; mt < 4; mt++)
#pragma unroll
            for (int nt = 0; nt < 4; nt++)
                mma_bf16(c[mt][nt], afh[mt], bfh[nt]);
#pragma unroll
        for (int mt = 0; mt < 4; mt++)
#pragma unroll
            for (int nt = 0; nt < 4; nt++)
                mma_bf16(c[mt][nt], afh[mt], bfl[nt]);
#pragma unroll
        for (int mt = 0; mt < 4; mt++)
#pragma unroll
            for (int nt = 0; nt < 4; nt++)
                mma_bf16(c[mt][nt], afl[mt], bfh[nt]);
    }
}

// ---------------- split fp32 -> bf16 hi/lo (vectorized x4) ---------------------
__global__ void split_kernel(const float* __restrict__ in,
                             __nv_bfloat16* __restrict__ hi,
                             __nv_bfloat16* __restrict__ lo, int n4) {
    int i = blockIdx.x * 256 + threadIdx.x;
    if (i >= n4) return;
    float4 v = reinterpret_cast<const float4*>(in)[i];
    __nv_bfloat16 hx = __float2bfloat16(v.x), hy = __float2bfloat16(v.y);
    __nv_bfloat16 hz = __float2bfloat16(v.z), hw = __float2bfloat16(v.w);
    __nv_bfloat162* h2 = reinterpret_cast<__nv_bfloat162*>(hi);
    __nv_bfloat162* l2 = reinterpret_cast<__nv_bfloat162*>(lo);
    h2[2 * i + 0] = __nv_bfloat162(hx, hy);
    h2[2 * i + 1] = __nv_bfloat162(hz, hw);
    l2[2 * i + 0] = __nv_bfloat162(__float2bfloat16(v.x - __bfloat162float(hx)),
                                   __float2bfloat16(v.y - __bfloat162float(hy)));
    l2[2 * i + 1] = __nv_bfloat162(__float2bfloat16(v.z - __bfloat162float(hz)),
                                   __float2bfloat16(v.w - __bfloat162float(hw)));
}

// ---------------- weight split: w2[o][s*768+i] = conv_w[o][i][s] ---------------
__global__ void wsplit_kernel(const float* __restrict__ w,
                              __nv_bfloat16* __restrict__ hi,
                              __nv_bfloat16* __restrict__ lo) {
    int gid = blockIdx.x * 256 + threadIdx.x;
    if (gid >= CC * K3) return;
    int o = gid / K3;
    int k = gid - o * K3;
    int s = k / CC;
    int i = k - s * CC;
    float v = w[(size_t)o * K3 + i * 3 + s];
    __nv_bfloat16 h = __float2bfloat16(v);
    hi[gid] = h;
    lo[gid] = __float2bfloat16(v - __bfloat162float(h));
}

__global__ void init_kernel(unsigned* dmax) {
    if (threadIdx.x < BB) dmax[threadIdx.x] = 0u;
}

// ---------------- conv GEMM (R11-exact): halo-A reuse, 2-stage, wait<0> --------
__global__ __launch_bounds__(256) void conv_mma_kernel(
    const float* __restrict__ x,
    const __nv_bfloat16* __restrict__ xh, const __nv_bfloat16* __restrict__ xl,
    const __nv_bfloat16* __restrict__ wh, const __nv_bfloat16* __restrict__ wl,
    float* __restrict__ y)
{
    extern __shared__ __nv_bfloat16 smem[];
    __nv_bfloat16* Abuf = smem;                       // 2 stages of halo A (hi+lo)
    __nv_bfloat16* Bbuf = smem + 2 * CONV_STAGE_A;    // 2 stages of B (hi+lo)
    const int tid = threadIdx.x;
    const int m0 = blockIdx.x * 128;
    const int n0 = blockIdx.y * 128;
    const int warp = tid >> 5, lane = tid & 31;
    const int wm = warp >> 2, wn = warp & 3;          // 2x4 warp grid, 64x32 tiles

    const int bz = m0 >> 11;
    const int tokbase = m0 & 2047;

    const int a_row = wm * 64 + (lane & 15);
    const int a_k   = (lane >> 4) * 8;
    const int b_row = wn * 32 + ((lane >> 4) & 1) * 8 + (lane & 7);
    const int b_k   = ((lane >> 3) & 1) * 8;

    const int lrow = tid >> 1, lhalf = (tid & 1) * 16;

    float c[4][4][4];
#pragma unroll
    for (int i = 0; i < 4; i++)
#pragma unroll
        for (int j = 0; j < 4; j++)
#pragma unroll
            for (int q = 0; q < 4; q++) c[i][j][q] = 0.f;

    // A halo tile: 130 rows, row r = token tokbase + r - 1 (zero-filled OOB)
    auto fillA = [&](int stage, int cch) {
        if (tid < 130) {
            const int tokloc = tokbase + tid - 1;
            const int ok = (tokloc >= 0 && tokloc < NN) ? 16 : 0;
            const int tc = tokloc < 0 ? 0 : (tokloc >= NN ? NN - 1 : tokloc);
            const __nv_bfloat16* gah = xh + ((size_t)(bz * NN + tc)) * CC + cch * 32;
            const __nv_bfloat16* gal = xl + ((size_t)(bz * NN + tc)) * CC + cch * 32;
            __nv_bfloat16* d = Abuf + stage * CONV_STAGE_A + tid * PADK;
#pragma unroll
            for (int j = 0; j < 4; j++) {
                cp16(d + j * 8, gah + j * 8, ok);
                cp16(d + CONV_A_ELEMS + j * 8, gal + j * 8, ok);
            }
        }
    };
    auto fillB = [&](int stage, int cch, int s) {
        const int k0 = s * CC + cch * 32;
        const __nv_bfloat16* gbh = wh + (size_t)(n0 + lrow) * K3 + k0 + lhalf;
        const __nv_bfloat16* gbl = wl + (size_t)(n0 + lrow) * K3 + k0 + lhalf;
        __nv_bfloat16* d = Bbuf + stage * CONV_STAGE_B + lrow * PADK + lhalf;
        cp16(d, gbh, 16);                  cp16(d + 8, gbh + 8, 16);
        cp16(d + 128 * PADK, gbl, 16);     cp16(d + 128 * PADK + 8, gbl + 8, 16);
    };

    const int NIT = 72;   // 24 channel chunks x 3 shifts (chunk-major)
    fillA(0, 0);
    fillB(0, 0, 0);
    cp_commit();
    for (int j = 0; j < NIT; j++) {
        const int cch = j / 3, s = j - 3 * cch;
        cp_wait<0>();
        __syncthreads();
        if (j + 1 < NIT) {
            const int c2 = (j + 1) / 3, s2 = (j + 1) - 3 * c2;
            fillB((j + 1) & 1, c2, s2);
            if (s2 == 0) fillA(c2 & 1, c2);
            cp_commit();
        }
        const __nv_bfloat16* Ast = Abuf + (cch & 1) * CONV_STAGE_A;
        const __nv_bfloat16* Bst = Bbuf + (j & 1) * CONV_STAGE_B;
        // shift s selects rows r = ml + s in the halo tile
        mma_slice(smem_u32(Ast) + s * PADK * 2,
                  smem_u32(Ast + CONV_A_ELEMS) + s * PADK * 2,
                  smem_u32(Bst), smem_u32(Bst + 128 * PADK),
                  a_row, a_k, b_row, b_k, c);
    }

    const int g = lane >> 2, t4 = lane & 3;
#pragma unroll
    for (int mt = 0; mt < 4; mt++) {
        int m = m0 + wm * 64 + mt * 16 + g;
        const float* xr0 = x + (size_t)m * CC;
        const float* xr1 = xr0 + (size_t)8 * CC;
        float* yr0 = y + (size_t)m * CC;
        float* yr1 = yr0 + (size_t)8 * CC;
#pragma unroll
        for (int nt = 0; nt < 4; nt++) {
            int n = n0 + wn * 32 + nt * 8 + t4 * 2;
            float2 xi0 = *reinterpret_cast<const float2*>(xr0 + n);
            float2 xi1 = *reinterpret_cast<const float2*>(xr1 + n);
            float2 o0, o1;
            o0.x = xi0.x + c[mt][nt][0]; o0.y = xi0.y + c[mt][nt][1];
            o1.x = xi1.x + c[mt][nt][2]; o1.y = xi1.y + c[mt][nt][3];
            *reinterpret_cast<float2*>(yr0 + n) = o0;
            *reinterpret_cast<float2*>(yr1 + n) = o1;
        }
    }
}

// ---------------- dist GEMM (symmetric) + fused knn partials (R9 config) -------
__global__ __launch_bounds__(256, 2) void dist_mma_kernel(
    const __nv_bfloat16* __restrict__ yh, const __nv_bfloat16* __restrict__ yl,
    const float* __restrict__ sq, float* __restrict__ dist,
    float* __restrict__ part, unsigned* __restrict__ dmax)
{
    extern __shared__ __nv_bfloat16 smem[];
    const int bx = blockIdx.x, by = blockIdx.y;
    if (by < bx) return;                         // lower triangle: mirrored from upper
    const int tid = threadIdx.x;
    const int bz = blockIdx.z;
    const int m0 = bx * 128;
    const int n0 = by * 128;
    const int warp = tid >> 5, lane = tid & 31;
    const int wm = warp >> 2, wn = warp & 3;

    const __nv_bfloat16* Xh = yh + (size_t)bz * NN * CC;
    const __nv_bfloat16* Xl = yl + (size_t)bz * NN * CC;

    const int lrow = tid >> 1, lhalf = (tid & 1) * 16;

    const int a_row = wm * 64 + (lane & 15);
    const int a_k   = (lane >> 4) * 8;
    const int b_row = wn * 32 + ((lane >> 4) & 1) * 8 + (lane & 7);
    const int b_k   = ((lane >> 3) & 1) * 8;

    float c[4][4][4];
#pragma unroll
    for (int i = 0; i < 4; i++)
#pragma unroll
        for (int j = 0; j < 4; j++)
#pragma unroll
            for (int q = 0; q < 4; q++) c[i][j][q] = 0.f;

    const int NIT = CC / 32;

    auto fill = [&](int stage, int k0) {
        __nv_bfloat16* stg = smem + stage * STAGE_ELEMS;
        const __nv_bfloat16* gah = Xh + (size_t)(m0 + lrow) * CC + k0 + lhalf;
        const __nv_bfloat16* gal = Xl + (size_t)(m0 + lrow) * CC + k0 + lhalf;
        const __nv_bfloat16* gbh = Xh + (size_t)(n0 + lrow) * CC + k0 + lhalf;
        const __nv_bfloat16* gbl = Xl + (size_t)(n0 + lrow) * CC + k0 + lhalf;
        __nv_bfloat16* d = stg + lrow * PADK + lhalf;
        cp16(d, gah, 16);                       cp16(d + 8, gah + 8, 16);
        cp16(d + MAT_ELEMS, gal, 16);           cp16(d + MAT_ELEMS + 8, gal + 8, 16);
        cp16(d + 2 * MAT_ELEMS, gbh, 16);       cp16(d + 2 * MAT_ELEMS + 8, gbh + 8, 16);
        cp16(d + 3 * MAT_ELEMS, gbl, 16);       cp16(d + 3 * MAT_ELEMS + 8, gbl + 8, 16);
    };

    fill(0, 0);
    cp_commit();
    for (int it = 0; it < NIT; it++) {
        cp_wait<0>();
        __syncthreads();
        if (it + 1 < NIT) { fill((it + 1) & 1, (it + 1) * 32); cp_commit(); }
        const __nv_bfloat16* stg = smem + (it & 1) * STAGE_ELEMS;
        mma_slice(smem_u32(stg), smem_u32(stg + MAT_ELEMS),
                  smem_u32(stg + 2 * MAT_ELEMS), smem_u32(stg + 3 * MAT_ELEMS),
                  a_row, a_k, b_row, b_k, c);
    }
    __syncthreads();   // all mma reads done before smem reuse as transpose buffer

    const float* sqb = sq + bz * NN;
    const int g = lane >> 2, t4 = lane & 3;
    float* tbuf = reinterpret_cast<float*>(smem);    // 128x129 fp32 transpose buffer
    float lmax = 0.f;
#pragma unroll
    for (int mt = 0; mt < 4; mt++) {
        int ml = wm * 64 + mt * 16 + g;              // local m row (and ml+8)
        int m = m0 + ml;
        float sm0 = sqb[m], sm1 = sqb[m + 8];
        float* dr0 = dist + ((size_t)bz * NN + m) * NN;
        float* dr1 = dr0 + (size_t)8 * NN;
        float p0 = 1e30f, p1 = 1e30f, p2 = 1e30f;    // row m top3 (this 32-col slice)
        float q0 = 1e30f, q1 = 1e30f, q2 = 1e30f;    // row m+8
#pragma unroll
        for (int nt = 0; nt < 4; nt++) {
            int nl = wn * 32 + nt * 8 + t4 * 2;      // local n col (and nl+1)
            int n = n0 + nl;
            float sn0 = sqb[n], sn1 = sqb[n + 1];
            float2 o0, o1;
            o0.x = sqrtf(fmaxf(sm0 + sn0 - 2.f * c[mt][nt][0], 0.f)) * RSC;
            o0.y = sqrtf(fmaxf(sm0 + sn1 - 2.f * c[mt][nt][1], 0.f)) * RSC;
            o1.x = sqrtf(fmaxf(sm1 + sn0 - 2.f * c[mt][nt][2], 0.f)) * RSC;
            o1.y = sqrtf(fmaxf(sm1 + sn1 - 2.f * c[mt][nt][3], 0.f)) * RSC;
            *reinterpret_cast<float2*>(dr0 + n) = o0;
            *reinterpret_cast<float2*>(dr1 + n) = o1;
            if (bx != by) {      // stage transposed values: tbuf[n_local][m_local]
                tbuf[(nl)     * 129 + ml]     = o0.x;
                tbuf[(nl + 1) * 129 + ml]     = o0.y;
                tbuf[(nl)     * 129 + ml + 8] = o1.x;
                tbuf[(nl + 1) * 129 + ml + 8] = o1.y;
            }
            ins3(o0.x, p0, p1, p2); ins3(o0.y, p0, p1, p2);
            ins3(o1.x, q0, q1, q2); ins3(o1.y, q0, q1, q2);
            lmax = fmaxf(lmax, fmaxf(fmaxf(o0.x, o0.y), fmaxf(o1.x, o1.y)));
        }
        // quad merge (lanes g*4+t4 share rows): top3 of 32 cols
#pragma unroll
        for (int off = 1; off <= 2; off <<= 1) {
            float a0 = __shfl_xor_sync(0xffffffffu, p0, off);
            float a1 = __shfl_xor_sync(0xffffffffu, p1, off);
            float a2 = __shfl_xor_sync(0xffffffffu, p2, off);
            ins3(a0, p0, p1, p2); ins3(a1, p0, p1, p2); ins3(a2, p0, p1, p2);
            float b0 = __shfl_xor_sync(0xffffffffu, q0, off);
            float b1 = __shfl_xor_sync(0xffffffffu, q1, off);
            float b2 = __shfl_xor_sync(0xffffffffu, q2, off);
            ins3(b0, q0, q1, q2); ins3(b1, q0, q1, q2); ins3(b2, q0, q1, q2);
        }
        if (t4 == 0) {
            float* pp = part + ((size_t)(bz * NN + m) * 64 + by * 4 + wn) * 3;
            pp[0] = p0; pp[1] = p1; pp[2] = p2;
            float* pq = part + ((size_t)(bz * NN + m + 8) * 64 + by * 4 + wn) * 3;
            pq[0] = q0; pq[1] = q1; pq[2] = q2;
        }
    }
#pragma unroll
    for (int off = 16; off; off >>= 1)
        lmax = fmaxf(lmax, __shfl_xor_sync(0xffffffffu, lmax, off));
    if (lane == 0) atomicMax(&dmax[bz], __float_as_uint(lmax));

    if (bx != by) {              // write mirrored tile + knn partials for rows n0..
        __syncthreads();
        const int r = tid >> 1;             // 0..127
        const int h = (tid & 1) * 64;       // half-row offset
        float* drow = dist + ((size_t)bz * NN + n0 + r) * NN + m0 + h;
        const float* srow = tbuf + r * 129 + h;
        float u0 = 1e30f, u1 = 1e30f, u2 = 1e30f;
#pragma unroll
        for (int j = 0; j < 16; j++) {
            float4 v = make_float4(srow[j * 4 + 0], srow[j * 4 + 1],
                                   srow[j * 4 + 2], srow[j * 4 + 3]);
            *reinterpret_cast<float4*>(drow + j * 4) = v;
            ins3(v.x, u0, u1, u2); ins3(v.y, u0, u1, u2);
            ins3(v.z, u0, u1, u2); ins3(v.w, u0, u1, u2);
        }
        float* pu = part + ((size_t)(bz * NN + n0 + r) * 64 + bx * 4 + (tid & 1)) * 3;
        pu[0] = u0; pu[1] = u1; pu[2] = u2;
        float* pv = part + ((size_t)(bz * NN + n0 + r) * 64 + bx * 4 + 2 + (tid & 1)) * 3;
        pv[0] = 1e30f; pv[1] = 1e30f; pv[2] = 1e30f;
    }
}

// ---------------- knn reduce: top3-of-partials -> density ----------------------
__global__ __launch_bounds__(256) void knn_reduce_kernel(
    const float* __restrict__ part, const float* __restrict__ noise,
    float* __restrict__ density)
{
    int row = (blockIdx.x * 256 + threadIdx.x) >> 5;   // one warp per row
    int lane = threadIdx.x & 31;
    const float* pr = part + (size_t)row * 192;
    float t0 = 1e30f, t1 = 1e30f, t2 = 1e30f;
#pragma unroll
    for (int j = 0; j < 6; j++) ins3(pr[lane + j * 32], t0, t1, t2);
#pragma unroll
    for (int off = 16; off; off >>= 1) {
        float a0 = __shfl_xor_sync(0xffffffffu, t0, off);
        float a1 = __shfl_xor_sync(0xffffffffu, t1, off);
        float a2 = __shfl_xor_sync(0xffffffffu, t2, off);
        ins3(a0, t0, t1, t2); ins3(a1, t0, t1, t2); ins3(a2, t0, t1, t2);
    }
    if (lane == 0) {
        float mean = (t0 * t0 + t1 * t1 + t2 * t2) * (1.0f / 3.0f);
        density[row] = expf(-mean) + noise[row] * 1e-6f;
    }
}

// ---------------- LayerNorm + score + weight + sq + bf16 split (fused) ---------
__global__ __launch_bounds__(256) void ln_kernel(
    float* __restrict__ y, const float* __restrict__ gamma, const float* __restrict__ beta,
    const float* __restrict__ sw, const float* __restrict__ sb,
    float* __restrict__ sq_out, float* __restrict__ w_out,
    __nv_bfloat16* __restrict__ yh, __nv_bfloat16* __restrict__ yl)
{
    int row = blockIdx.x;
    int tid = threadIdx.x;
    __shared__ float ws[8], ws2[8];
    float* xr = y + (size_t)row * CC;
    float v0 = xr[tid], v1 = xr[tid + 256], v2 = xr[tid + 512];

    float s = v0 + v1 + v2;
#pragma unroll
    for (int o = 16; o; o >>= 1) s += __shfl_xor_sync(0xffffffffu, s, o);
    if ((tid & 31) == 0) ws[tid >> 5] = s;
    __syncthreads();
    float mu = (ws[0] + ws[1] + ws[2] + ws[3] + ws[4] + ws[5] + ws[6] + ws[7]) * (1.0f / CC);

    float d0 = v0 - mu, d1 = v1 - mu, d2 = v2 - mu;
    float q = d0 * d0 + d1 * d1 + d2 * d2;
#pragma unroll
    for (int o = 16; o; o >>= 1) q += __shfl_xor_sync(0xffffffffu, q, o);
    __syncthreads();
    if ((tid & 31) == 0) ws[tid >> 5] = q;
    __syncthreads();
    float var = (ws[0] + ws[1] + ws[2] + ws[3] + ws[4] + ws[5] + ws[6] + ws[7]) * (1.0f / CC);
    float inv = 1.0f / sqrtf(var + 1e-5f);

    float x0 = d0 * inv * gamma[tid]       + beta[tid];
    float x1 = d1 * inv * gamma[tid + 256] + beta[tid + 256];
    float x2 = d2 * inv * gamma[tid + 512] + beta[tid + 512];
    xr[tid] = x0; xr[tid + 256] = x1; xr[tid + 512] = x2;

    __nv_bfloat16* hr = yh + (size_t)row * CC;
    __nv_bfloat16* lr = yl + (size_t)row * CC;
    __nv_bfloat16 h0 = __float2bfloat16(x0), h1 = __float2bfloat16(x1), h2 = __float2bfloat16(x2);
    hr[tid] = h0; hr[tid + 256] = h1; hr[tid + 512] = h2;
    lr[tid]       = __float2bfloat16(x0 - __bfloat162float(h0));
    lr[tid + 256] = __float2bfloat16(x1 - __bfloat162float(h1));
    lr[tid + 512] = __float2bfloat16(x2 - __bfloat162float(h2));

    float a = x0 * x0 + x1 * x1 + x2 * x2;
    float b = x0 * sw[tid] + x1 * sw[tid + 256] + x2 * sw[tid + 512];
#pragma unroll
    for (int o = 16; o; o >>= 1) {
        a += __shfl_xor_sync(0xffffffffu, a, o);
        b += __shfl_xor_sync(0xffffffffu, b, o);
    }
    __syncthreads();
    if ((tid & 31) == 0) { ws[tid >> 5] = a; ws2[tid >> 5] = b; }
    __syncthreads();
    if (tid == 0) {
        sq_out[row] = ws[0] + ws[1] + ws[2] + ws[3] + ws[4] + ws[5] + ws[6] + ws[7];
        w_out[row]  = expf(ws2[0] + ws2[1] + ws2[2] + ws2[3] + ws2[4] + ws2[5] + ws2[6] + ws2[7] + sb[0]);
    }
}

// ---------------- dist_min (4 rows per block: share density row) ---------------
__global__ __launch_bounds__(256) void distmin_kernel(
    const float* __restrict__ dist, const float* __restrict__ density,
    const unsigned* __restrict__ dmax, float* __restrict__ score)
{
    int r0 = blockIdx.x * 4;
    int tid = threadIdx.x;
    int b = r0 >> 11;
    const float4* db = reinterpret_cast<const float4*>(density + b * NN);
    float dn[4], lmin[4];
    float dm = __uint_as_float(dmax[b]);
#pragma unroll
    for (int r = 0; r < 4; r++) { dn[r] = density[r0 + r]; lmin[r] = dm; }
#pragma unroll
    for (int it = 0; it < 2; it++) {
        float4 rho = db[tid + it * 256];
#pragma unroll
        for (int r = 0; r < 4; r++) {
            const float4* dr = reinterpret_cast<const float4*>(dist + (size_t)(r0 + r) * NN);
            float4 d = dr[tid + it * 256];
            if (rho.x > dn[r]) lmin[r] = fminf(lmin[r], d.x);
            if (rho.y > dn[r]) lmin[r] = fminf(lmin[r], d.y);
            if (rho.z > dn[r]) lmin[r] = fminf(lmin[r], d.z);
            if (rho.w > dn[r]) lmin[r] = fminf(lmin[r], d.w);
        }
    }
    __shared__ float red[4][256];
#pragma unroll
    for (int r = 0; r < 4; r++) red[r][tid] = lmin[r];
    __syncthreads();
    for (int s = 128; s > 0; s >>= 1) {
        if (tid < s) {
#pragma unroll
            for (int r = 0; r < 4; r++) red[r][tid] = fminf(red[r][tid], red[r][tid + s]);
        }
        __syncthreads();
    }
    if (tid < 4) score[r0 + tid] = red[tid][0] * dn[tid];
}

// ---------------- per-batch top-2 (ties -> lower index) -----------------------
__global__ __launch_bounds__(256) void top2_kernel(const float* __restrict__ score, int* __restrict__ centers) {
    int b = blockIdx.x, tid = threadIdx.x;
    const float* sc = score + b * NN;
    __shared__ float sv[256];
    __shared__ int   si[256];
    float bv = -1e30f; int bi = 0;
    for (int n = tid; n < NN; n += 256) { float v = sc[n]; if (v > bv) { bv = v; bi = n; } }
    sv[tid] = bv; si[tid] = bi;
    __syncthreads();
    for (int s = 128; s > 0; s >>= 1) {
        if (tid < s) {
            if (sv[tid + s] > sv[tid] || (sv[tid + s] == sv[tid] && si[tid + s] < si[tid])) {
                sv[tid] = sv[tid + s]; si[tid] = si[tid + s];
            }
        }
        __syncthreads();
    }
    int c0 = si[0];
    __syncthreads();
    bv = -1e30f; bi = 0;
    for (int n = tid; n < NN; n += 256) {
        if (n == c0) continue;
        float v = sc[n]; if (v > bv) { bv = v; bi = n; }
    }
    sv[tid] = bv; si[tid] = bi;
    __syncthreads();
    for (int s = 128; s > 0; s >>= 1) {
        if (tid < s) {
            if (sv[tid + s] > sv[tid] || (sv[tid + s] == sv[tid] && si[tid + s] < si[tid])) {
                sv[tid] = sv[tid + s]; si[tid] = si[tid + s];
            }
        }
        __syncthreads();
    }
    if (tid == 0) { centers[2 * b] = c0; centers[2 * b + 1] = si[0]; }
}

// ---------------- cluster assignment ------------------------------------------
__global__ void assign_kernel(const float* __restrict__ dist, const int* __restrict__ centers,
                              int* __restrict__ idxc) {
    int gid = blockIdx.x * 256 + threadIdx.x;
    if (gid >= MTOT) return;
    int b = gid >> 11, n = gid & 2047;
    int c0 = centers[2 * b], c1 = centers[2 * b + 1];
    float d0 = dist[((size_t)b * NN + c0) * NN + n];
    float d1 = dist[((size_t)b * NN + c1) * NN + n];
    int id = (d0 <= d1) ? 0 : 1;
    if (n == c0) id = 0;
    if (n == c1) id = 1;
    idxc[gid] = id;
}

// ---------------- all_weight per (b,cluster) ----------------------------------
__global__ __launch_bounds__(256) void allw_kernel(
    const float* __restrict__ weight, const int* __restrict__ idxc, float* __restrict__ allw)
{
    int b = blockIdx.x, tid = threadIdx.x;
    float w0 = 0.f, w1 = 0.f;
    for (int n = tid; n < NN; n += 256) {
        float w = weight[b * NN + n];
        if (idxc[b * NN + n] == 0) w0 += w; else w1 += w;
    }
    __shared__ float r0[256], r1[256];
    r0[tid] = w0; r1[tid] = w1;
    __syncthreads();
    for (int s = 128; s > 0; s >>= 1) {
        if (tid < s) { r0[tid] += r0[tid + s]; r1[tid] += r1[tid + s]; }
        __syncthreads();
    }
    if (tid == 0) { allw[2 * b] = r0[0] + 1e-6f; allw[2 * b + 1] = r1[0] + 1e-6f; }
}

// ---------------- weighted merge: deterministic two-stage (R11 version) --------
__global__ __launch_bounds__(256) void merge_partial_kernel(
    const float* __restrict__ x, const float* __restrict__ weight,
    const int* __restrict__ idxc, const float* __restrict__ allw, float* __restrict__ partial)
{
    int chunk = blockIdx.x;
    int cl = blockIdx.y;
    int b = blockIdx.z;
    int tid = threadIdx.x;
    float aw = allw[b * 2 + cl];
    float a0 = 0.f, a1 = 0.f, a2 = 0.f;
    for (int j = 0; j < 128; j++) {
        int n = chunk * 128 + j;
        if (idxc[b * NN + n] == cl) {
            float w = weight[b * NN + n] / aw;
            const float* xr = x + ((size_t)b * NN + n) * CC;
            a0 += w * xr[tid];
            a1 += w * xr[tid + 256];
            a2 += w * xr[tid + 512];
        }
    }
    float* p = partial + (((size_t)(b * 2 + cl) * 16 + chunk)) * CC;
    p[tid] = a0; p[tid + 256] = a1; p[tid + 512] = a2;
}

__global__ __launch_bounds__(256) void merge_reduce_kernel(
    const float* __restrict__ partial, float* __restrict__ out)
{
    int g = blockIdx.x;
    int tid = threadIdx.x;
#pragma unroll
    for (int t = 0; t < 3; t++) {
        int ch = tid + t * 256;
        float s = 0.f;
        for (int c = 0; c < 16; c++)
            s += partial[((size_t)g * 16 + c) * CC + ch];
        out[(size_t)g * CC + ch] = s;
    }
}

// ---------------- finalize agg_weight + idx outputs ---------------------------
__global__ void finalize_kernel(const float* __restrict__ weight, const int* __restrict__ idxc,
                                const float* __restrict__ allw, float* __restrict__ out)
{
    int gid = blockIdx.x * 256 + threadIdx.x;
    if (gid >= MTOT) return;
    int b = gid >> 11;
    int id = idxc[gid];
    float nw = weight[gid] / allw[b * 2 + id];
    out[24576 + gid] = nw;
    out[57344 + gid] = (float)id;
}

// ------------------------------ launch ----------------------------------------
extern "C" void kernel_launch(void* const* d_in, const int* in_sizes, int n_in,
                              void* d_out, int out_size) {
    const float* x      = (const float*)d_in[0];
    const float* conv_w = (const float*)d_in[1];
    const float* gamma  = (const float*)d_in[2];
    const float* beta   = (const float*)d_in[3];
    const float* sw     = (const float*)d_in[4];
    const float* sb     = (const float*)d_in[5];
    const float* noise  = (const float*)d_in[6];
    float* out = (float*)d_out;

    __nv_bfloat16 *xh, *xl, *wh, *wl, *yh, *yl;
    float *y, *dist, *knn3, *sq, *weight, *density, *score, *allw, *partial;
    unsigned* dmax; int *centers, *idxc;
    cudaGetSymbolAddress((void**)&xh, g_xh);
    cudaGetSymbolAddress((void**)&xl, g_xl);
    cudaGetSymbolAddress((void**)&wh, g_wh);
    cudaGetSymbolAddress((void**)&wl, g_wl);
    cudaGetSymbolAddress((void**)&yh, g_yh);
    cudaGetSymbolAddress((void**)&yl, g_yl);
    cudaGetSymbolAddress((void**)&y, g_y);
    cudaGetSymbolAddress((void**)&dist, g_dist);
    cudaGetSymbolAddress((void**)&knn3, g_knn3);
    cudaGetSymbolAddress((void**)&sq, g_sq);
    cudaGetSymbolAddress((void**)&weight, g_weight);
    cudaGetSymbolAddress((void**)&density, g_density);
    cudaGetSymbolAddress((void**)&score, g_score);
    cudaGetSymbolAddress((void**)&dmax, g_distmax);
    cudaGetSymbolAddress((void**)&centers, g_centers);
    cudaGetSymbolAddress((void**)&idxc, g_idxc);
    cudaGetSymbolAddress((void**)&allw, g_allw);
    cudaGetSymbolAddress((void**)&partial, g_partial);

    // opt-in to >48KB dynamic smem; only outside graph capture (attr persists)
    cudaStreamCaptureStatus cstat = cudaStreamCaptureStatusNone;
    cudaStreamIsCapturing(0, &cstat);
    if (cstat == cudaStreamCaptureStatusNone) {
        cudaFuncSetAttribute(conv_mma_kernel, cudaFuncAttributeMaxDynamicSharedMemorySize, CONV_SMEM);
        cudaFuncSetAttribute(dist_mma_kernel, cudaFuncAttributeMaxDynamicSharedMemorySize, SMEM_BYTES);
    }

    const int n4 = MTOT * CC / 4;

    wsplit_kernel<<<(CC * K3 + 255) / 256, 256>>>(conv_w, wh, wl);
    split_kernel<<<(n4 + 255) / 256, 256>>>(x, xh, xl, n4);
    init_kernel<<<1, 32>>>(dmax);
    conv_mma_kernel<<<dim3(MTOT / 128, CC / 128), 256, CONV_SMEM>>>(x, xh, xl, wh, wl, y);
    ln_kernel<<<MTOT, 256>>>(y, gamma, beta, sw, sb, sq, weight, yh, yl);
    dist_mma_kernel<<<dim3(NN / 128, NN / 128, BB), 256, SMEM_BYTES>>>(yh, yl, sq, dist, knn3, dmax);
    knn_reduce_kernel<<<MTOT * 32 / 256, 256>>>(knn3, noise, density);
    distmin_kernel<<<MTOT / 4, 256>>>(dist, density, dmax, score);
    top2_kernel<<<BB, 256>>>(score, centers);
    assign_kernel<<<MTOT / 256, 256>>>(dist, centers, idxc);
    allw_kernel<<<BB, 256>>>(weight, idxc, allw);
    merge_partial_kernel<<<dim3(16, 2, BB), 256>>>(y, weight, idxc, allw, partial);
    merge_reduce_kernel<<<BB * 2, 256>>>(partial, out);
    finalize_kernel<<<MTOT / 256, 256>>>(weight, idxc, allw, out);
}